// round 13
// baseline (speedup 1.0000x reference)
#include <cuda_runtime.h>
#include <cuda_bf16.h>
#include <math.h>

// ---------------- problem constants (match dataset) ----------------
#define NMAXN 100000
#define EMAXE 1600000
#define HID 128
#define NOUT 10
#define BN_EPS 1e-5f
#define SCAN_B 1024

// ---------------- static device scratch (alloc-free rule) ----------------
__device__ __align__(256) float g_bufB[(size_t)NMAXN * HID]; // gemm output (pre-scaled msg)
__device__ __align__(256) float g_bufC[(size_t)NMAXN * HID]; // aggregation output
__device__ __align__(256) int   g_cnt[NMAXN];
__device__ __align__(256) int   g_rowstart[NMAXN + 1];
__device__ __align__(256) int   g_cursor[NMAXN];
__device__ __align__(256) int   g_src_sorted[EMAXE];
__device__ __align__(256) float g_dinv[NMAXN];
__device__ __align__(256) float g_cs[2][HID];   // per-layer column sums
__device__ __align__(256) float g_cq[2][HID];   // per-layer column sumsq
__device__ __align__(256) float g_scale[HID];
__device__ __align__(256) float g_shift[HID];
__device__ __align__(256) int   g_partials[256];
__device__ int g_aggdone[2];   // grid-completion counters for agg128 (per layer)
// pre-split W (hi/lo bf16), transposed to [n][k] (n-major), both 128-wide layers
__device__ __align__(256) __nv_bfloat16 g_Wh[2][HID * HID];
__device__ __align__(256) __nv_bfloat16 g_Wl[2][HID * HID];
__device__ int g_is64;   // 1 if edge_index is int64, 0 if int32

__device__ __forceinline__ int edge_at(const void* ei, size_t idx) {
    if (g_is64) return (int)((const long long*)ei)[idx];
    return ((const int*)ei)[idx];
}

// ---------------- fused init: zero + dtype detect + W split (both layers) ----------------
// int64 nonneg small indices (little-endian): every odd 32-bit word is 0.
__global__ void k_init(const unsigned int* __restrict__ raw,
                       const float* __restrict__ W0, const float* __restrict__ W1,
                       int n)
{
    int i = blockIdx.x * blockDim.x + threadIdx.x;
    if (i < n) { g_cnt[i] = 0; g_cursor[i] = 0; }
    if (i < HID) {
        g_cs[0][i] = 0.f; g_cq[0][i] = 0.f;
        g_cs[1][i] = 0.f; g_cq[1][i] = 0.f;
    }
    if (i < 2) g_aggdone[i] = 0;
    // W split: first 32768 threads
    if (i < 2 * HID * HID) {
        int layer = i >> 14;
        int r = i & 16383;
        int k = r >> 7, nn = r & 127;
        float v = (layer ? W1 : W0)[r];
        __nv_bfloat16 h = __float2bfloat16_rn(v);
        __nv_bfloat16 l = __float2bfloat16_rn(v - __bfloat162float(h));
        g_Wh[layer][nn * HID + k] = h;
        g_Wl[layer][nn * HID + k] = l;
    }
    // dtype detect: block 0
    if (blockIdx.x == 0) {
        __shared__ int any;
        if (threadIdx.x == 0) any = 0;
        __syncthreads();
        unsigned int w = raw[threadIdx.x * 2 + 1];   // first 512 words
        if (w != 0u) atomicOr(&any, 1);
        __syncthreads();
        if (threadIdx.x == 0) g_is64 = any ? 0 : 1;
    }
}

// ---------------- edge counting: vectorized (e % 4 == 0) + scalar fallback ----------------
__global__ void k_count4(const void* __restrict__ ei, int e, int n) {
    int i = blockIdx.x * blockDim.x + threadIdx.x;   // vector index, 4 edges each
    int nv = e >> 2;
    if (i >= nv) return;
    int d0, d1, d2, d3;
    if (g_is64) {
        const long long* dst = (const long long*)ei + e;
        longlong2 a = ((const longlong2*)dst)[i * 2];
        longlong2 b = ((const longlong2*)dst)[i * 2 + 1];
        d0 = (int)a.x; d1 = (int)a.y; d2 = (int)b.x; d3 = (int)b.y;
    } else {
        const int* dst = (const int*)ei + e;
        int4 a = ((const int4*)dst)[i];
        d0 = a.x; d1 = a.y; d2 = a.z; d3 = a.w;
    }
    if ((unsigned)d0 < (unsigned)n) atomicAdd(&g_cnt[d0], 1);
    if ((unsigned)d1 < (unsigned)n) atomicAdd(&g_cnt[d1], 1);
    if ((unsigned)d2 < (unsigned)n) atomicAdd(&g_cnt[d2], 1);
    if ((unsigned)d3 < (unsigned)n) atomicAdd(&g_cnt[d3], 1);
}

__global__ void k_count(const void* __restrict__ ei, int e, int n) {
    int i = blockIdx.x * blockDim.x + threadIdx.x;
    if (i < e) {
        int d = edge_at(ei, (size_t)e + i);
        if ((unsigned)d < (unsigned)n) atomicAdd(&g_cnt[d], 1);
    }
}

// ---------------- scan: stage 1 (per-block inclusive) + finalize ----------------
__global__ void k_scan1(int n) {
    __shared__ int sh[SCAN_B];
    int i = blockIdx.x * SCAN_B + threadIdx.x;
    int v = (i < n) ? g_cnt[i] : 0;
    sh[threadIdx.x] = v;
    __syncthreads();
    for (int off = 1; off < SCAN_B; off <<= 1) {
        int t = 0;
        if ((int)threadIdx.x >= off) t = sh[threadIdx.x - off];
        __syncthreads();
        if ((int)threadIdx.x >= off) sh[threadIdx.x] += t;
        __syncthreads();
    }
    if (i < n) g_rowstart[i] = sh[threadIdx.x];
    if (threadIdx.x == SCAN_B - 1) g_partials[blockIdx.x] = sh[SCAN_B - 1];
}

// finalize: each block redundantly scans the <=128 block partials in smem,
// then computes exclusive row starts + dinv.
__global__ __launch_bounds__(256) void k_scan3(int n, int nb) {
    __shared__ int sp[128];
    int tid = threadIdx.x;
    if (tid < 128) sp[tid] = (tid < nb) ? g_partials[tid] : 0;
    __syncthreads();
    for (int off = 1; off < 128; off <<= 1) {
        int v = 0;
        if (tid < 128 && tid >= off) v = sp[tid - off];
        __syncthreads();
        if (tid < 128 && tid >= off) sp[tid] += v;
        __syncthreads();
    }
    int i = blockIdx.x * blockDim.x + tid;
    if (i < n) {
        int b = i / SCAN_B;
        int excl = (b == 0) ? 0 : sp[b - 1];
        int cnt  = g_cnt[i];
        int incl = g_rowstart[i] + excl;
        g_rowstart[i] = incl - cnt;
        if (i == n - 1) g_rowstart[n] = incl;
        g_dinv[i] = rsqrtf((float)cnt + 1.0f);
    }
}

// ---------------- bucketing: vectorized (e % 4 == 0) + scalar fallback ----------------
__global__ void k_bucket4(const void* __restrict__ ei, int e, int n) {
    int i = blockIdx.x * blockDim.x + threadIdx.x;
    int nv = e >> 2;
    if (i >= nv) return;
    int s0, s1, s2, s3, d0, d1, d2, d3;
    if (g_is64) {
        const long long* src = (const long long*)ei;
        const long long* dst = src + e;
        longlong2 sa = ((const longlong2*)src)[i * 2];
        longlong2 sb = ((const longlong2*)src)[i * 2 + 1];
        longlong2 da = ((const longlong2*)dst)[i * 2];
        longlong2 db = ((const longlong2*)dst)[i * 2 + 1];
        s0 = (int)sa.x; s1 = (int)sa.y; s2 = (int)sb.x; s3 = (int)sb.y;
        d0 = (int)da.x; d1 = (int)da.y; d2 = (int)db.x; d3 = (int)db.y;
    } else {
        const int* src = (const int*)ei;
        const int* dst = src + e;
        int4 sa = ((const int4*)src)[i];
        int4 da = ((const int4*)dst)[i];
        s0 = sa.x; s1 = sa.y; s2 = sa.z; s3 = sa.w;
        d0 = da.x; d1 = da.y; d2 = da.z; d3 = da.w;
    }
    if ((unsigned)d0 < (unsigned)n && (unsigned)s0 < (unsigned)n)
        g_src_sorted[g_rowstart[d0] + atomicAdd(&g_cursor[d0], 1)] = s0;
    if ((unsigned)d1 < (unsigned)n && (unsigned)s1 < (unsigned)n)
        g_src_sorted[g_rowstart[d1] + atomicAdd(&g_cursor[d1], 1)] = s1;
    if ((unsigned)d2 < (unsigned)n && (unsigned)s2 < (unsigned)n)
        g_src_sorted[g_rowstart[d2] + atomicAdd(&g_cursor[d2], 1)] = s2;
    if ((unsigned)d3 < (unsigned)n && (unsigned)s3 < (unsigned)n)
        g_src_sorted[g_rowstart[d3] + atomicAdd(&g_cursor[d3], 1)] = s3;
}

__global__ void k_bucket(const void* __restrict__ ei, int e, int n) {
    int i = blockIdx.x * blockDim.x + threadIdx.x;
    if (i < e) {
        int s = edge_at(ei, i);
        int d = edge_at(ei, (size_t)e + i);
        if ((unsigned)d < (unsigned)n && (unsigned)s < (unsigned)n) {
            int pos = atomicAdd(&g_cursor[d], 1);
            g_src_sorted[g_rowstart[d] + pos] = s;
        }
    }
}

// ---------------- Tensor-core GEMM: msg = dinv * ([n,128] @ [128,128]) -> g_bufB ----------------
// R8/R11 VERBATIM (register profile is load-bearing — do not add prologues).
// mode==1: A = relu(g_bufC * g_scale + g_shift).
#define GMB 128
#define GKB 32
#define GSTR 40   // bf16 stride: 80B = 20 words -> conflict-free fragment loads

__device__ __forceinline__ void mma_bf16(
    float& c0, float& c1, float& c2, float& c3,
    unsigned a0, unsigned a1, unsigned a2, unsigned a3,
    unsigned b0, unsigned b1)
{
    asm volatile(
        "mma.sync.aligned.m16n8k16.row.col.f32.bf16.bf16.f32 "
        "{%0,%1,%2,%3}, {%4,%5,%6,%7}, {%8,%9}, {%0,%1,%2,%3};"
        : "+f"(c0), "+f"(c1), "+f"(c2), "+f"(c3)
        : "r"(a0), "r"(a1), "r"(a2), "r"(a3), "r"(b0), "r"(b1));
}

__device__ __forceinline__ __nv_bfloat162 split2(float a, float b, __nv_bfloat162& lo) {
    __nv_bfloat16 ha = __float2bfloat16_rn(a);
    __nv_bfloat16 hb = __float2bfloat16_rn(b);
    __nv_bfloat16 la = __float2bfloat16_rn(a - __bfloat162float(ha));
    __nv_bfloat16 lb = __float2bfloat16_rn(b - __bfloat162float(hb));
    lo = __halves2bfloat162(la, lb);
    return __halves2bfloat162(ha, hb);
}

__global__ __launch_bounds__(256) void k_gemm_tc(
    const float* __restrict__ Aext, int mode, int layer, int n)
{
    __shared__ __align__(16) __nv_bfloat16 Ah[GMB][GSTR];
    __shared__ __align__(16) __nv_bfloat16 Al[GMB][GSTR];
    __shared__ __align__(16) __nv_bfloat16 Wh[HID][GSTR];  // [n][k-chunk]
    __shared__ __align__(16) __nv_bfloat16 Wl[HID][GSTR];

    int tid  = threadIdx.x;
    int warp = tid >> 5;
    int lane = tid & 31;
    int group = lane >> 2;      // 0..7
    int tig   = lane & 3;       // 0..3
    int wm = (warp >> 1) * 32;  // warp row offset 0/32/64/96
    int wn = (warp & 1) * 64;   // warp col offset 0/64
    int br = blockIdx.x * GMB;
    const float* A = mode ? (const float*)g_bufC : Aext;
    const __nv_bfloat16* GWh = g_Wh[layer];
    const __nv_bfloat16* GWl = g_Wl[layer];

    float acc[2][8][4];
#pragma unroll
    for (int mi = 0; mi < 2; mi++)
#pragma unroll
        for (int j = 0; j < 8; j++)
#pragma unroll
            for (int q = 0; q < 4; q++) acc[mi][j][q] = 0.f;

    for (int kb = 0; kb < HID; kb += GKB) {
        // ---- load + split A chunk: 128 rows x 32 k ----
#pragma unroll
        for (int u = 0; u < 4; u++) {
            int idx = tid + u * 256;        // 0..1023 float4 slots
            int row = idx >> 3;             // 0..127
            int c4  = idx & 7;              // 0..7
            int gr  = br + row;
            float4 v = make_float4(0.f, 0.f, 0.f, 0.f);
            if (gr < n) v = ((const float4*)A)[(size_t)gr * 32 + (kb >> 2) + c4];
            if (mode) {
                float4 sc = ((const float4*)g_scale)[(kb >> 2) + c4];
                float4 sh = ((const float4*)g_shift)[(kb >> 2) + c4];
                v.x = fmaxf(fmaf(v.x, sc.x, sh.x), 0.f);
                v.y = fmaxf(fmaf(v.y, sc.y, sh.y), 0.f);
                v.z = fmaxf(fmaf(v.z, sc.z, sh.z), 0.f);
                v.w = fmaxf(fmaf(v.w, sc.w, sh.w), 0.f);
            }
            int kc = c4 * 4;
            __nv_bfloat162 lo0, lo1;
            __nv_bfloat162 hi0 = split2(v.x, v.y, lo0);
            __nv_bfloat162 hi1 = split2(v.z, v.w, lo1);
            *(__nv_bfloat162*)&Ah[row][kc]     = hi0;
            *(__nv_bfloat162*)&Ah[row][kc + 2] = hi1;
            *(__nv_bfloat162*)&Al[row][kc]     = lo0;
            *(__nv_bfloat162*)&Al[row][kc + 2] = lo1;
        }
        // ---- copy pre-split W chunk: 128 n-rows x 32 k, pure int4 copies ----
#pragma unroll
        for (int u = 0; u < 2; u++) {
            int idx = tid + u * 256;
            int nr = idx >> 2;              // 0..127
            int q  = idx & 3;               // 0..3
            *(int4*)&Wh[nr][q * 8] = *(const int4*)&GWh[nr * HID + kb + q * 8];
            *(int4*)&Wl[nr][q * 8] = *(const int4*)&GWl[nr * HID + kb + q * 8];
        }
        __syncthreads();

#pragma unroll
        for (int ks = 0; ks < 2; ks++) {
            int k0 = ks * 16;
            int ac0 = k0 + tig * 2, ac1 = k0 + tig * 2 + 8;
            unsigned ah[2][4], al[2][4];
#pragma unroll
            for (int mi = 0; mi < 2; mi++) {
                int ar0 = wm + mi * 16 + group, ar1 = ar0 + 8;
                ah[mi][0] = *(const unsigned*)&Ah[ar0][ac0];
                ah[mi][1] = *(const unsigned*)&Ah[ar1][ac0];
                ah[mi][2] = *(const unsigned*)&Ah[ar0][ac1];
                ah[mi][3] = *(const unsigned*)&Ah[ar1][ac1];
                al[mi][0] = *(const unsigned*)&Al[ar0][ac0];
                al[mi][1] = *(const unsigned*)&Al[ar1][ac0];
                al[mi][2] = *(const unsigned*)&Al[ar0][ac1];
                al[mi][3] = *(const unsigned*)&Al[ar1][ac1];
            }
#pragma unroll
            for (int j = 0; j < 8; j++) {
                int nr = wn + j * 8 + group;
                unsigned bh0 = *(const unsigned*)&Wh[nr][ac0];
                unsigned bh1 = *(const unsigned*)&Wh[nr][ac1];
                unsigned bl0 = *(const unsigned*)&Wl[nr][ac0];
                unsigned bl1 = *(const unsigned*)&Wl[nr][ac1];
#pragma unroll
                for (int mi = 0; mi < 2; mi++) {
                    mma_bf16(acc[mi][j][0], acc[mi][j][1], acc[mi][j][2], acc[mi][j][3],
                             ah[mi][0], ah[mi][1], ah[mi][2], ah[mi][3], bh0, bh1);
                    mma_bf16(acc[mi][j][0], acc[mi][j][1], acc[mi][j][2], acc[mi][j][3],
                             ah[mi][0], ah[mi][1], ah[mi][2], ah[mi][3], bl0, bl1);
                    mma_bf16(acc[mi][j][0], acc[mi][j][1], acc[mi][j][2], acc[mi][j][3],
                             al[mi][0], al[mi][1], al[mi][2], al[mi][3], bh0, bh1);
                }
            }
        }
        __syncthreads();
    }
    // ---- store msg = dinv[row] * C ----
#pragma unroll
    for (int mi = 0; mi < 2; mi++) {
        int row0 = br + wm + mi * 16 + group;
        int row1 = row0 + 8;
        float d0 = (row0 < n) ? g_dinv[row0] : 0.f;
        float d1 = (row1 < n) ? g_dinv[row1] : 0.f;
#pragma unroll
        for (int j = 0; j < 8; j++) {
            int col = wn + j * 8 + tig * 2;
            if (row0 < n) *(float2*)&g_bufB[(size_t)row0 * HID + col]
                = make_float2(d0 * acc[mi][j][0], d0 * acc[mi][j][1]);
            if (row1 < n) *(float2*)&g_bufB[(size_t)row1 * HID + col]
                = make_float2(d1 * acc[mi][j][2], d1 * acc[mi][j][3]);
        }
    }
}

// ---------------- small GEMM: msg10 = dinv * (relu(bn(g_bufC)) @ W2) -> g_bufB[n,10] ----------------
__global__ __launch_bounds__(256) void k_gemm10(
    const float* __restrict__ W, int n)
{
    __shared__ float Ws[HID * NOUT];
    int tid = threadIdx.x;
    for (int i = tid; i < HID * NOUT; i += blockDim.x) Ws[i] = W[i];
    __syncthreads();
    int warp = tid >> 5, lane = tid & 31;
    int row = blockIdx.x * (blockDim.x >> 5) + warp;
    if (row >= n) return;
    const float* A = (const float*)g_bufC;
    float a0 = fmaxf(fmaf(A[(size_t)row * HID + lane],      g_scale[lane],      g_shift[lane]),      0.f);
    float a1 = fmaxf(fmaf(A[(size_t)row * HID + 32 + lane], g_scale[lane + 32], g_shift[lane + 32]), 0.f);
    float a2 = fmaxf(fmaf(A[(size_t)row * HID + 64 + lane], g_scale[lane + 64], g_shift[lane + 64]), 0.f);
    float a3 = fmaxf(fmaf(A[(size_t)row * HID + 96 + lane], g_scale[lane + 96], g_shift[lane + 96]), 0.f);
    float di = g_dinv[row];
#pragma unroll
    for (int c = 0; c < NOUT; c++) {
        float p = a0 * Ws[lane * NOUT + c]
                + a1 * Ws[(lane + 32) * NOUT + c]
                + a2 * Ws[(lane + 64) * NOUT + c]
                + a3 * Ws[(lane + 96) * NOUT + c];
#pragma unroll
        for (int off = 16; off > 0; off >>= 1)
            p += __shfl_down_sync(0xffffffffu, p, off);
        if (lane == 0) g_bufB[(size_t)row * NOUT + c] = di * p;
    }
}

// ---------------- aggregation + fused BN stats + fused BN finalize (last block) ----------------
// msg is pre-scaled: out[i] = dinv[i] * (sum_{src} msg[src] + msg[i]) + bias
// The LAST block to finish also computes g_scale/g_shift from the completed
// g_cs/g_cq — removes the standalone k_bnfinal launch. (Fusing this into the
// GEMM cost 70us via a register cliff, R9-R11; agg is memory-bound and safe.)
__global__ __launch_bounds__(256) void k_agg128(
    const float* __restrict__ bias,
    const float* __restrict__ gamma, const float* __restrict__ beta,
    int n, int layer)
{
    __shared__ float shs[8][HID];
    __shared__ float shq[8][HID];
    __shared__ int isLast;
    int ty = threadIdx.y;
    int lane = threadIdx.x;
    int node = blockIdx.x * 8 + ty;
    bool active = node < n;
    const float4* hp = (const float4*)g_bufB;

    float4 o = make_float4(0.f, 0.f, 0.f, 0.f);
    if (active) {
        float di = g_dinv[node];
        float4 acc = hp[(size_t)node * 32 + lane];      // msg[node] (self-loop)
        int beg = g_rowstart[node], end = g_rowstart[node + 1];
        int j = beg;
        for (; j + 3 < end; j += 4) {
            int s0 = g_src_sorted[j];
            int s1 = g_src_sorted[j + 1];
            int s2 = g_src_sorted[j + 2];
            int s3 = g_src_sorted[j + 3];
            float4 m0 = hp[(size_t)s0 * 32 + lane];
            float4 m1 = hp[(size_t)s1 * 32 + lane];
            float4 m2 = hp[(size_t)s2 * 32 + lane];
            float4 m3 = hp[(size_t)s3 * 32 + lane];
            acc.x += (m0.x + m1.x) + (m2.x + m3.x);
            acc.y += (m0.y + m1.y) + (m2.y + m3.y);
            acc.z += (m0.z + m1.z) + (m2.z + m3.z);
            acc.w += (m0.w + m1.w) + (m2.w + m3.w);
        }
        for (; j < end; j++) {
            int s = g_src_sorted[j];
            float4 m = hp[(size_t)s * 32 + lane];
            acc.x += m.x; acc.y += m.y; acc.z += m.z; acc.w += m.w;
        }
        float4 bb = ((const float4*)bias)[lane];
        o.x = fmaf(di, acc.x, bb.x); o.y = fmaf(di, acc.y, bb.y);
        o.z = fmaf(di, acc.z, bb.z); o.w = fmaf(di, acc.w, bb.w);
        ((float4*)g_bufC)[(size_t)node * 32 + lane] = o;
    }

    // block-local column reduction, then one atomic per column
    *(float4*)&shs[ty][lane * 4] = o;
    *(float4*)&shq[ty][lane * 4] = make_float4(o.x * o.x, o.y * o.y, o.z * o.z, o.w * o.w);
    __syncthreads();
    int tid = ty * 32 + lane;
    if (tid < HID) {
        float s = 0.f, q = 0.f;
#pragma unroll
        for (int r = 0; r < 8; r++) { s += shs[r][tid]; q += shq[r][tid]; }
        atomicAdd(&g_cs[layer][tid], s);
        atomicAdd(&g_cq[layer][tid], q);
    }
    // grid-completion: last block computes BN scale/shift from finished stats
    if (tid == 0) {
        __threadfence();
        int done = atomicAdd(&g_aggdone[layer], 1);
        isLast = (done == (int)gridDim.x - 1) ? 1 : 0;
    }
    __syncthreads();
    if (isLast && tid < HID) {
        float inv_n = 1.0f / (float)n;
        float mu  = g_cs[layer][tid] * inv_n;
        float var = fmaxf(g_cq[layer][tid] * inv_n - mu * mu, 0.0f);
        float sc = gamma[tid] * rsqrtf(var + BN_EPS);
        g_scale[tid] = sc;
        g_shift[tid] = fmaf(-mu, sc, beta[tid]);
    }
}

// width-10 final agg: two edges per iteration (lane halves), writes d_out
__global__ __launch_bounds__(256) void k_agg10(
    const float* __restrict__ bias, float* __restrict__ out, int n)
{
    int ty = threadIdx.y;
    int lane = threadIdx.x;
    int node = blockIdx.x * 8 + ty;
    if (node >= n) return;
    int half = lane >> 4;       // 0/1
    int c = lane & 15;          // column, active c < NOUT
    const float* h = (const float*)g_bufB;
    float di = g_dinv[node];
    float acc = 0.f;
    if (half == 0 && c < NOUT) acc = h[(size_t)node * NOUT + c];  // self msg
    int beg = g_rowstart[node], end = g_rowstart[node + 1];
    for (int j = beg + half; j < end; j += 2) {
        int s = g_src_sorted[j];
        if (c < NOUT) acc += h[(size_t)s * NOUT + c];
    }
    acc += __shfl_xor_sync(0xffffffffu, acc, 16);
    if (half == 0 && c < NOUT)
        out[(size_t)node * NOUT + c] = fmaf(di, acc, bias[c]);
}

// ---------------- host launcher: kernel launches ONLY ----------------
extern "C" void kernel_launch(void* const* d_in, const int* in_sizes, int n_in,
                              void* d_out, int out_size)
{
    const float* x  = (const float*)d_in[0];
    const void*  ei = d_in[1];
    const float* W0 = (const float*)d_in[2];  const float* b0 = (const float*)d_in[3];
    const float* g0 = (const float*)d_in[4];  const float* be0 = (const float*)d_in[5];
    const float* W1 = (const float*)d_in[6];  const float* b1 = (const float*)d_in[7];
    const float* g1 = (const float*)d_in[8];  const float* be1 = (const float*)d_in[9];
    const float* W2 = (const float*)d_in[10]; const float* b2 = (const float*)d_in[11];

    int n = in_sizes[0] / HID;
    int e = in_sizes[1] / 2;
    float* out = (float*)d_out;

    int nb_n256 = (n + 255) / 256;
    int nb_scan = (n + SCAN_B - 1) / SCAN_B;

    // ---- init + CSR build (5 launches) ----
    k_init<<<nb_n256, 256>>>((const unsigned int*)ei, W0, W1, n);
    if ((e & 3) == 0) {
        int nb_v = ((e >> 2) + 255) / 256;
        k_count4<<<nb_v, 256>>>(ei, e, n);
        k_scan1<<<nb_scan, SCAN_B>>>(n);
        k_scan3<<<nb_n256, 256>>>(n, nb_scan);
        k_bucket4<<<nb_v, 256>>>(ei, e, n);
    } else {
        int nb_e256 = (e + 255) / 256;
        k_count<<<nb_e256, 256>>>(ei, e, n);
        k_scan1<<<nb_scan, SCAN_B>>>(n);
        k_scan3<<<nb_n256, 256>>>(n, nb_scan);
        k_bucket<<<nb_e256, 256>>>(ei, e, n);
    }

    dim3 aggBlk(32, 8);
    int aggGrid = (n + 7) / 8;
    int gemmGrid = (n + GMB - 1) / GMB;

    // ---- layer 0 ----
    k_gemm_tc<<<gemmGrid, 256>>>(x, 0, 0, n);
    k_agg128<<<aggGrid, aggBlk>>>(b0, g0, be0, n, 0);   // last block writes BN0 scale/shift

    // ---- layer 1 (BN0 apply fused into A-load) ----
    k_gemm_tc<<<gemmGrid, 256>>>(x, 1, 1, n);
    k_agg128<<<aggGrid, aggBlk>>>(b1, g1, be1, n, 1);   // last block writes BN1 scale/shift

    // ---- layer 2 (BN1 apply fused into A-load; output) ----
    k_gemm10<<<(n + 7) / 8, 256>>>(W2, n);
    k_agg10<<<aggGrid, aggBlk>>>(b2, out, n);
}

// round 14
// speedup vs baseline: 1.0758x; 1.0758x over previous
#include <cuda_runtime.h>
#include <cuda_bf16.h>
#include <math.h>

// ---------------- problem constants (match dataset) ----------------
#define NMAXN 100000
#define EMAXE 1600000
#define HID 128
#define NOUT 10
#define BN_EPS 1e-5f
#define CSRB 148        // resident-grid CSR kernel: one block per SM, wave-1 guaranteed
#define CSRT 1024

// ---------------- static device scratch (alloc-free rule) ----------------
__device__ __align__(256) float g_bufB[(size_t)NMAXN * HID]; // gemm output (pre-scaled msg)
__device__ __align__(256) float g_bufC[(size_t)NMAXN * HID]; // aggregation output
__device__ __align__(256) int   g_cnt[NMAXN];
__device__ __align__(256) int   g_rowstart[NMAXN + 1];
__device__ __align__(256) int   g_cursor[NMAXN];
__device__ __align__(256) int   g_src_sorted[EMAXE];
__device__ __align__(256) float g_dinv[NMAXN];
__device__ __align__(256) float g_cs[2][HID];   // per-layer column sums
__device__ __align__(256) float g_cq[2][HID];   // per-layer column sumsq
__device__ __align__(256) float g_scale[HID];
__device__ __align__(256) float g_shift[HID];
__device__ __align__(256) int   g_partials[128];
__device__ int g_barcnt;     // monotonic global-barrier counter for k_csr
// pre-split W (hi/lo bf16), transposed to [n][k] (n-major), both 128-wide layers
__device__ __align__(256) __nv_bfloat16 g_Wh[2][HID * HID];
__device__ __align__(256) __nv_bfloat16 g_Wl[2][HID * HID];
__device__ int g_is64;   // 1 if edge_index is int64, 0 if int32

__device__ __forceinline__ int edge_at(const void* ei, size_t idx) {
    if (g_is64) return (int)((const long long*)ei)[idx];
    return ((const int*)ei)[idx];
}

// ---------------- fused init: zero + dtype detect + W split (both layers) ----------------
// int64 nonneg small indices (little-endian): every odd 32-bit word is 0.
__global__ void k_init(const unsigned int* __restrict__ raw,
                       const float* __restrict__ W0, const float* __restrict__ W1,
                       int n)
{
    int i = blockIdx.x * blockDim.x + threadIdx.x;
    if (i < n) { g_cnt[i] = 0; g_cursor[i] = 0; }
    if (i < HID) {
        g_cs[0][i] = 0.f; g_cq[0][i] = 0.f;
        g_cs[1][i] = 0.f; g_cq[1][i] = 0.f;
    }
    if (i == 0) g_barcnt = 0;
    // W split: first 32768 threads
    if (i < 2 * HID * HID) {
        int layer = i >> 14;
        int r = i & 16383;
        int k = r >> 7, nn = r & 127;
        float v = (layer ? W1 : W0)[r];
        __nv_bfloat16 h = __float2bfloat16_rn(v);
        __nv_bfloat16 l = __float2bfloat16_rn(v - __bfloat162float(h));
        g_Wh[layer][nn * HID + k] = h;
        g_Wl[layer][nn * HID + k] = l;
    }
    // dtype detect: block 0
    if (blockIdx.x == 0) {
        __shared__ int any;
        if (threadIdx.x == 0) any = 0;
        __syncthreads();
        unsigned int w = raw[threadIdx.x * 2 + 1];   // first 512 words
        if (w != 0u) atomicOr(&any, 1);
        __syncthreads();
        if (threadIdx.x == 0) g_is64 = any ? 0 : 1;
    }
}

// ---------------- one-kernel CSR build (count -> scan -> bucket) ----------------
// 148 blocks x 1024 threads, all wave-1 resident -> software global barrier is safe.
// Monotonic counter barrier: no reset, no race; g_barcnt zeroed by k_init each call.
__device__ __forceinline__ void gbar(int phase) {
    __syncthreads();
    if (threadIdx.x == 0) {
        __threadfence();                       // make this block's stores visible
        atomicAdd(&g_barcnt, 1);
        while (atomicAdd(&g_barcnt, 0) < phase * CSRB) { }
    }
    __syncthreads();
}

__global__ __launch_bounds__(CSRT) void k_csr(const void* __restrict__ ei, int e, int n) {
    __shared__ int sh[CSRT];
    __shared__ int sp[128];
    int tid = threadIdx.x;
    int b = blockIdx.x;
    int gsz = CSRB * CSRT;

    // ---- phase A: degree count (grid-stride) ----
    for (int j = b * CSRT + tid; j < e; j += gsz) {
        int d = edge_at(ei, (size_t)e + j);
        if ((unsigned)d < (unsigned)n) atomicAdd(&g_cnt[d], 1);
    }
    gbar(1);

    // ---- phase B: per-chunk inclusive scan; publish chunk totals ----
    int nbc = (n + CSRT - 1) / CSRT;           // <= 128 for n <= 131072
    int i = b * CSRT + tid;
    int cnt = 0;
    if (b < nbc) {
        cnt = (i < n) ? g_cnt[i] : 0;
        sh[tid] = cnt;
        __syncthreads();
        for (int off = 1; off < CSRT; off <<= 1) {
            int t = (tid >= off) ? sh[tid - off] : 0;
            __syncthreads();
            if (tid >= off) sh[tid] += t;
            __syncthreads();
        }
        if (tid == CSRT - 1) g_partials[b] = sh[CSRT - 1];
    }
    gbar(2);

    // ---- phase C: chunk-offset scan (redundant per block) + rowstart + dinv ----
    if (b < nbc) {
        if (tid < 128) sp[tid] = (tid < nbc) ? g_partials[tid] : 0;
        __syncthreads();
        for (int off = 1; off < 128; off <<= 1) {
            int v = (tid < 128 && tid >= off) ? sp[tid - off] : 0;
            __syncthreads();
            if (tid < 128 && tid >= off) sp[tid] += v;
            __syncthreads();
        }
        if (i < n) {
            int excl = (b == 0) ? 0 : sp[b - 1];
            int incl = sh[tid] + excl;
            g_rowstart[i] = incl - cnt;
            if (i == n - 1) g_rowstart[n] = incl;
            g_dinv[i] = rsqrtf((float)cnt + 1.0f);
        }
    }
    gbar(3);

    // ---- phase D: bucket (grid-stride) ----
    for (int j = b * CSRT + tid; j < e; j += gsz) {
        int s = edge_at(ei, j);
        int d = edge_at(ei, (size_t)e + j);
        if ((unsigned)d < (unsigned)n && (unsigned)s < (unsigned)n) {
            int pos = atomicAdd(&g_cursor[d], 1);
            g_src_sorted[g_rowstart[d] + pos] = s;
        }
    }
}

// ---------------- Tensor-core GEMM: msg = dinv * ([n,128] @ [128,128]) -> g_bufB ----------------
// R8/R11 VERBATIM (register profile is load-bearing — do not add prologues/epilogues).
// mode==1: A = relu(g_bufC * g_scale + g_shift).
#define GMB 128
#define GKB 32
#define GSTR 40   // bf16 stride: 80B = 20 words -> conflict-free fragment loads

__device__ __forceinline__ void mma_bf16(
    float& c0, float& c1, float& c2, float& c3,
    unsigned a0, unsigned a1, unsigned a2, unsigned a3,
    unsigned b0, unsigned b1)
{
    asm volatile(
        "mma.sync.aligned.m16n8k16.row.col.f32.bf16.bf16.f32 "
        "{%0,%1,%2,%3}, {%4,%5,%6,%7}, {%8,%9}, {%0,%1,%2,%3};"
        : "+f"(c0), "+f"(c1), "+f"(c2), "+f"(c3)
        : "r"(a0), "r"(a1), "r"(a2), "r"(a3), "r"(b0), "r"(b1));
}

__device__ __forceinline__ __nv_bfloat162 split2(float a, float b, __nv_bfloat162& lo) {
    __nv_bfloat16 ha = __float2bfloat16_rn(a);
    __nv_bfloat16 hb = __float2bfloat16_rn(b);
    __nv_bfloat16 la = __float2bfloat16_rn(a - __bfloat162float(ha));
    __nv_bfloat16 lb = __float2bfloat16_rn(b - __bfloat162float(hb));
    lo = __halves2bfloat162(la, lb);
    return __halves2bfloat162(ha, hb);
}

__global__ __launch_bounds__(256) void k_gemm_tc(
    const float* __restrict__ Aext, int mode, int layer, int n)
{
    __shared__ __align__(16) __nv_bfloat16 Ah[GMB][GSTR];
    __shared__ __align__(16) __nv_bfloat16 Al[GMB][GSTR];
    __shared__ __align__(16) __nv_bfloat16 Wh[HID][GSTR];  // [n][k-chunk]
    __shared__ __align__(16) __nv_bfloat16 Wl[HID][GSTR];

    int tid  = threadIdx.x;
    int warp = tid >> 5;
    int lane = tid & 31;
    int group = lane >> 2;      // 0..7
    int tig   = lane & 3;       // 0..3
    int wm = (warp >> 1) * 32;  // warp row offset 0/32/64/96
    int wn = (warp & 1) * 64;   // warp col offset 0/64
    int br = blockIdx.x * GMB;
    const float* A = mode ? (const float*)g_bufC : Aext;
    const __nv_bfloat16* GWh = g_Wh[layer];
    const __nv_bfloat16* GWl = g_Wl[layer];

    float acc[2][8][4];
#pragma unroll
    for (int mi = 0; mi < 2; mi++)
#pragma unroll
        for (int j = 0; j < 8; j++)
#pragma unroll
            for (int q = 0; q < 4; q++) acc[mi][j][q] = 0.f;

    for (int kb = 0; kb < HID; kb += GKB) {
        // ---- load + split A chunk: 128 rows x 32 k ----
#pragma unroll
        for (int u = 0; u < 4; u++) {
            int idx = tid + u * 256;        // 0..1023 float4 slots
            int row = idx >> 3;             // 0..127
            int c4  = idx & 7;              // 0..7
            int gr  = br + row;
            float4 v = make_float4(0.f, 0.f, 0.f, 0.f);
            if (gr < n) v = ((const float4*)A)[(size_t)gr * 32 + (kb >> 2) + c4];
            if (mode) {
                float4 sc = ((const float4*)g_scale)[(kb >> 2) + c4];
                float4 sh = ((const float4*)g_shift)[(kb >> 2) + c4];
                v.x = fmaxf(fmaf(v.x, sc.x, sh.x), 0.f);
                v.y = fmaxf(fmaf(v.y, sc.y, sh.y), 0.f);
                v.z = fmaxf(fmaf(v.z, sc.z, sh.z), 0.f);
                v.w = fmaxf(fmaf(v.w, sc.w, sh.w), 0.f);
            }
            int kc = c4 * 4;
            __nv_bfloat162 lo0, lo1;
            __nv_bfloat162 hi0 = split2(v.x, v.y, lo0);
            __nv_bfloat162 hi1 = split2(v.z, v.w, lo1);
            *(__nv_bfloat162*)&Ah[row][kc]     = hi0;
            *(__nv_bfloat162*)&Ah[row][kc + 2] = hi1;
            *(__nv_bfloat162*)&Al[row][kc]     = lo0;
            *(__nv_bfloat162*)&Al[row][kc + 2] = lo1;
        }
        // ---- copy pre-split W chunk: 128 n-rows x 32 k, pure int4 copies ----
#pragma unroll
        for (int u = 0; u < 2; u++) {
            int idx = tid + u * 256;
            int nr = idx >> 2;              // 0..127
            int q  = idx & 3;               // 0..3
            *(int4*)&Wh[nr][q * 8] = *(const int4*)&GWh[nr * HID + kb + q * 8];
            *(int4*)&Wl[nr][q * 8] = *(const int4*)&GWl[nr * HID + kb + q * 8];
        }
        __syncthreads();

#pragma unroll
        for (int ks = 0; ks < 2; ks++) {
            int k0 = ks * 16;
            int ac0 = k0 + tig * 2, ac1 = k0 + tig * 2 + 8;
            unsigned ah[2][4], al[2][4];
#pragma unroll
            for (int mi = 0; mi < 2; mi++) {
                int ar0 = wm + mi * 16 + group, ar1 = ar0 + 8;
                ah[mi][0] = *(const unsigned*)&Ah[ar0][ac0];
                ah[mi][1] = *(const unsigned*)&Ah[ar1][ac0];
                ah[mi][2] = *(const unsigned*)&Ah[ar0][ac1];
                ah[mi][3] = *(const unsigned*)&Ah[ar1][ac1];
                al[mi][0] = *(const unsigned*)&Al[ar0][ac0];
                al[mi][1] = *(const unsigned*)&Al[ar1][ac0];
                al[mi][2] = *(const unsigned*)&Al[ar0][ac1];
                al[mi][3] = *(const unsigned*)&Al[ar1][ac1];
            }
#pragma unroll
            for (int j = 0; j < 8; j++) {
                int nr = wn + j * 8 + group;
                unsigned bh0 = *(const unsigned*)&Wh[nr][ac0];
                unsigned bh1 = *(const unsigned*)&Wh[nr][ac1];
                unsigned bl0 = *(const unsigned*)&Wl[nr][ac0];
                unsigned bl1 = *(const unsigned*)&Wl[nr][ac1];
#pragma unroll
                for (int mi = 0; mi < 2; mi++) {
                    mma_bf16(acc[mi][j][0], acc[mi][j][1], acc[mi][j][2], acc[mi][j][3],
                             ah[mi][0], ah[mi][1], ah[mi][2], ah[mi][3], bh0, bh1);
                    mma_bf16(acc[mi][j][0], acc[mi][j][1], acc[mi][j][2], acc[mi][j][3],
                             ah[mi][0], ah[mi][1], ah[mi][2], ah[mi][3], bl0, bl1);
                    mma_bf16(acc[mi][j][0], acc[mi][j][1], acc[mi][j][2], acc[mi][j][3],
                             al[mi][0], al[mi][1], al[mi][2], al[mi][3], bh0, bh1);
                }
            }
        }
        __syncthreads();
    }
    // ---- store msg = dinv[row] * C ----
#pragma unroll
    for (int mi = 0; mi < 2; mi++) {
        int row0 = br + wm + mi * 16 + group;
        int row1 = row0 + 8;
        float d0 = (row0 < n) ? g_dinv[row0] : 0.f;
        float d1 = (row1 < n) ? g_dinv[row1] : 0.f;
#pragma unroll
        for (int j = 0; j < 8; j++) {
            int col = wn + j * 8 + tig * 2;
            if (row0 < n) *(float2*)&g_bufB[(size_t)row0 * HID + col]
                = make_float2(d0 * acc[mi][j][0], d0 * acc[mi][j][1]);
            if (row1 < n) *(float2*)&g_bufB[(size_t)row1 * HID + col]
                = make_float2(d1 * acc[mi][j][2], d1 * acc[mi][j][3]);
        }
    }
}

// ---------------- small GEMM: msg10 = dinv * (relu(bn(g_bufC)) @ W2) -> g_bufB[n,10] ----------------
__global__ __launch_bounds__(256) void k_gemm10(
    const float* __restrict__ W, int n)
{
    __shared__ float Ws[HID * NOUT];
    int tid = threadIdx.x;
    for (int i = tid; i < HID * NOUT; i += blockDim.x) Ws[i] = W[i];
    __syncthreads();
    int warp = tid >> 5, lane = tid & 31;
    int row = blockIdx.x * (blockDim.x >> 5) + warp;
    if (row >= n) return;
    const float* A = (const float*)g_bufC;
    float a0 = fmaxf(fmaf(A[(size_t)row * HID + lane],      g_scale[lane],      g_shift[lane]),      0.f);
    float a1 = fmaxf(fmaf(A[(size_t)row * HID + 32 + lane], g_scale[lane + 32], g_shift[lane + 32]), 0.f);
    float a2 = fmaxf(fmaf(A[(size_t)row * HID + 64 + lane], g_scale[lane + 64], g_shift[lane + 64]), 0.f);
    float a3 = fmaxf(fmaf(A[(size_t)row * HID + 96 + lane], g_scale[lane + 96], g_shift[lane + 96]), 0.f);
    float di = g_dinv[row];
#pragma unroll
    for (int c = 0; c < NOUT; c++) {
        float p = a0 * Ws[lane * NOUT + c]
                + a1 * Ws[(lane + 32) * NOUT + c]
                + a2 * Ws[(lane + 64) * NOUT + c]
                + a3 * Ws[(lane + 96) * NOUT + c];
#pragma unroll
        for (int off = 16; off > 0; off >>= 1)
            p += __shfl_down_sync(0xffffffffu, p, off);
        if (lane == 0) g_bufB[(size_t)row * NOUT + c] = di * p;
    }
}

// ---------------- aggregation + fused BN stats, width 128 (R11 VERBATIM) ----------------
// msg is pre-scaled: out[i] = dinv[i] * (sum_{src} msg[src] + msg[i]) + bias
__global__ __launch_bounds__(256) void k_agg128(
    const float* __restrict__ bias, int n, int layer)
{
    __shared__ float shs[8][HID];
    __shared__ float shq[8][HID];
    int ty = threadIdx.y;
    int lane = threadIdx.x;
    int node = blockIdx.x * 8 + ty;
    bool active = node < n;
    const float4* hp = (const float4*)g_bufB;

    float4 o = make_float4(0.f, 0.f, 0.f, 0.f);
    if (active) {
        float di = g_dinv[node];
        float4 acc = hp[(size_t)node * 32 + lane];      // msg[node] (self-loop)
        int beg = g_rowstart[node], end = g_rowstart[node + 1];
        int j = beg;
        for (; j + 3 < end; j += 4) {
            int s0 = g_src_sorted[j];
            int s1 = g_src_sorted[j + 1];
            int s2 = g_src_sorted[j + 2];
            int s3 = g_src_sorted[j + 3];
            float4 m0 = hp[(size_t)s0 * 32 + lane];
            float4 m1 = hp[(size_t)s1 * 32 + lane];
            float4 m2 = hp[(size_t)s2 * 32 + lane];
            float4 m3 = hp[(size_t)s3 * 32 + lane];
            acc.x += (m0.x + m1.x) + (m2.x + m3.x);
            acc.y += (m0.y + m1.y) + (m2.y + m3.y);
            acc.z += (m0.z + m1.z) + (m2.z + m3.z);
            acc.w += (m0.w + m1.w) + (m2.w + m3.w);
        }
        for (; j < end; j++) {
            int s = g_src_sorted[j];
            float4 m = hp[(size_t)s * 32 + lane];
            acc.x += m.x; acc.y += m.y; acc.z += m.z; acc.w += m.w;
        }
        float4 bb = ((const float4*)bias)[lane];
        o.x = fmaf(di, acc.x, bb.x); o.y = fmaf(di, acc.y, bb.y);
        o.z = fmaf(di, acc.z, bb.z); o.w = fmaf(di, acc.w, bb.w);
        ((float4*)g_bufC)[(size_t)node * 32 + lane] = o;
    }

    *(float4*)&shs[ty][lane * 4] = o;
    *(float4*)&shq[ty][lane * 4] = make_float4(o.x * o.x, o.y * o.y, o.z * o.z, o.w * o.w);
    __syncthreads();
    int tid = ty * 32 + lane;
    if (tid < HID) {
        float s = 0.f, q = 0.f;
#pragma unroll
        for (int r = 0; r < 8; r++) { s += shs[r][tid]; q += shq[r][tid]; }
        atomicAdd(&g_cs[layer][tid], s);
        atomicAdd(&g_cq[layer][tid], q);
    }
}

// width-10 final agg: two edges per iteration (lane halves), writes d_out
__global__ __launch_bounds__(256) void k_agg10(
    const float* __restrict__ bias, float* __restrict__ out, int n)
{
    int ty = threadIdx.y;
    int lane = threadIdx.x;
    int node = blockIdx.x * 8 + ty;
    if (node >= n) return;
    int half = lane >> 4;       // 0/1
    int c = lane & 15;          // column, active c < NOUT
    const float* h = (const float*)g_bufB;
    float di = g_dinv[node];
    float acc = 0.f;
    if (half == 0 && c < NOUT) acc = h[(size_t)node * NOUT + c];  // self msg
    int beg = g_rowstart[node], end = g_rowstart[node + 1];
    for (int j = beg + half; j < end; j += 2) {
        int s = g_src_sorted[j];
        if (c < NOUT) acc += h[(size_t)s * NOUT + c];
    }
    acc += __shfl_xor_sync(0xffffffffu, acc, 16);
    if (half == 0 && c < NOUT)
        out[(size_t)node * NOUT + c] = fmaf(di, acc, bias[c]);
}

// ---------------- BN finalize (standalone — fusing into hot kernels regresses, R9/R13) ----------------
__global__ __launch_bounds__(128) void k_bnfinal(
    const float* __restrict__ g, const float* __restrict__ be,
    int layer, int n)
{
    int c = threadIdx.x;
    float inv_n = 1.0f / (float)n;
    float mu  = g_cs[layer][c] * inv_n;
    float var = fmaxf(g_cq[layer][c] * inv_n - mu * mu, 0.0f);
    float sc = g[c] * rsqrtf(var + BN_EPS);
    g_scale[c] = sc;
    g_shift[c] = fmaf(-mu, sc, be[c]);
}

// ---------------- host launcher: kernel launches ONLY ----------------
extern "C" void kernel_launch(void* const* d_in, const int* in_sizes, int n_in,
                              void* d_out, int out_size)
{
    const float* x  = (const float*)d_in[0];
    const void*  ei = d_in[1];
    const float* W0 = (const float*)d_in[2];  const float* b0 = (const float*)d_in[3];
    const float* g0 = (const float*)d_in[4];  const float* be0 = (const float*)d_in[5];
    const float* W1 = (const float*)d_in[6];  const float* b1 = (const float*)d_in[7];
    const float* g1 = (const float*)d_in[8];  const float* be1 = (const float*)d_in[9];
    const float* W2 = (const float*)d_in[10]; const float* b2 = (const float*)d_in[11];

    int n = in_sizes[0] / HID;
    int e = in_sizes[1] / 2;
    float* out = (float*)d_out;

    int nb_n256 = (n + 255) / 256;

    // ---- init(1) + one-kernel CSR(2) ----
    k_init<<<nb_n256, 256>>>((const unsigned int*)ei, W0, W1, n);
    k_csr<<<CSRB, CSRT>>>(ei, e, n);

    dim3 aggBlk(32, 8);
    int aggGrid = (n + 7) / 8;
    int gemmGrid = (n + GMB - 1) / GMB;

    // ---- layer 0: gemm(3), agg(4 <- ncu-profiled slot) ----
    k_gemm_tc<<<gemmGrid, 256>>>(x, 0, 0, n);
    k_agg128<<<aggGrid, aggBlk>>>(b0, n, 0);
    k_bnfinal<<<1, 128>>>(g0, be0, 0, n);

    // ---- layer 1 (BN0 apply fused into A-load) ----
    k_gemm_tc<<<gemmGrid, 256>>>(x, 1, 1, n);
    k_agg128<<<aggGrid, aggBlk>>>(b1, n, 1);
    k_bnfinal<<<1, 128>>>(g1, be1, 1, n);

    // ---- layer 2 (BN1 apply fused into A-load; output) ----
    k_gemm10<<<(n + 7) / 8, 256>>>(W2, n);
    k_agg10<<<aggGrid, aggBlk>>>(b2, out, n);
}

// round 15
// speedup vs baseline: 1.1069x; 1.0288x over previous
#include <cuda_runtime.h>
#include <cuda_bf16.h>
#include <math.h>

// ---------------- problem constants (match dataset) ----------------
#define NMAXN 100000
#define EMAXE 1600000
#define HID 128
#define NOUT 10
#define BN_EPS 1e-5f
#define SCAN_B 1024

// ---------------- static device scratch (alloc-free rule) ----------------
__device__ __align__(256) float g_bufB[(size_t)NMAXN * HID]; // gemm output (pre-scaled msg)
__device__ __align__(256) float g_bufC[(size_t)NMAXN * HID]; // aggregation output
__device__ __align__(256) int   g_cnt[NMAXN];
__device__ __align__(256) int   g_rowstart[NMAXN + 1];
__device__ __align__(256) int   g_cursor[NMAXN];
__device__ __align__(256) int   g_src_sorted[EMAXE];
__device__ __align__(256) float g_dinv[NMAXN];
__device__ __align__(256) float g_cs[2][HID];   // per-layer column sums
__device__ __align__(256) float g_cq[2][HID];   // per-layer column sumsq
__device__ __align__(256) float g_scale[HID];
__device__ __align__(256) float g_shift[HID];
__device__ __align__(256) int   g_partials[128];
// pre-split W (hi/lo bf16), transposed to [n][k] (n-major), both 128-wide layers
__device__ __align__(256) __nv_bfloat16 g_Wh[2][HID * HID];
__device__ __align__(256) __nv_bfloat16 g_Wl[2][HID * HID];
__device__ int g_is64;   // 1 if edge_index is int64, 0 if int32

__device__ __forceinline__ int edge_at(const void* ei, size_t idx) {
    if (g_is64) return (int)((const long long*)ei)[idx];
    return ((const int*)ei)[idx];
}

// ---------------- fused init: zero + dtype detect + W split (both layers) ----------------
__global__ void k_init(const unsigned int* __restrict__ raw,
                       const float* __restrict__ W0, const float* __restrict__ W1,
                       int n)
{
    int i = blockIdx.x * blockDim.x + threadIdx.x;
    if (i < n) { g_cnt[i] = 0; g_cursor[i] = 0; }
    if (i < HID) {
        g_cs[0][i] = 0.f; g_cq[0][i] = 0.f;
        g_cs[1][i] = 0.f; g_cq[1][i] = 0.f;
    }
    if (i < 2 * HID * HID) {
        int layer = i >> 14;
        int r = i & 16383;
        int k = r >> 7, nn = r & 127;
        float v = (layer ? W1 : W0)[r];
        __nv_bfloat16 h = __float2bfloat16_rn(v);
        __nv_bfloat16 l = __float2bfloat16_rn(v - __bfloat162float(h));
        g_Wh[layer][nn * HID + k] = h;
        g_Wl[layer][nn * HID + k] = l;
    }
    if (blockIdx.x == 0) {
        __shared__ int any;
        if (threadIdx.x == 0) any = 0;
        __syncthreads();
        unsigned int w = raw[threadIdx.x * 2 + 1];
        if (w != 0u) atomicOr(&any, 1);
        __syncthreads();
        if (threadIdx.x == 0) g_is64 = any ? 0 : 1;
    }
}

// ---------------- edge counting: vectorized (e % 4 == 0) + scalar fallback ----------------
__global__ void k_count4(const void* __restrict__ ei, int e, int n) {
    int i = blockIdx.x * blockDim.x + threadIdx.x;
    int nv = e >> 2;
    if (i >= nv) return;
    int d0, d1, d2, d3;
    if (g_is64) {
        const long long* dst = (const long long*)ei + e;
        longlong2 a = ((const longlong2*)dst)[i * 2];
        longlong2 b = ((const longlong2*)dst)[i * 2 + 1];
        d0 = (int)a.x; d1 = (int)a.y; d2 = (int)b.x; d3 = (int)b.y;
    } else {
        const int* dst = (const int*)ei + e;
        int4 a = ((const int4*)dst)[i];
        d0 = a.x; d1 = a.y; d2 = a.z; d3 = a.w;
    }
    if ((unsigned)d0 < (unsigned)n) atomicAdd(&g_cnt[d0], 1);
    if ((unsigned)d1 < (unsigned)n) atomicAdd(&g_cnt[d1], 1);
    if ((unsigned)d2 < (unsigned)n) atomicAdd(&g_cnt[d2], 1);
    if ((unsigned)d3 < (unsigned)n) atomicAdd(&g_cnt[d3], 1);
}

__global__ void k_count(const void* __restrict__ ei, int e, int n) {
    int i = blockIdx.x * blockDim.x + threadIdx.x;
    if (i < e) {
        int d = edge_at(ei, (size_t)e + i);
        if ((unsigned)d < (unsigned)n) atomicAdd(&g_cnt[d], 1);
    }
}

// ---------------- scan: per-block inclusive + finalize (inlined partial scan) ----------------
__global__ void k_scan1(int n) {
    __shared__ int sh[SCAN_B];
    int i = blockIdx.x * SCAN_B + threadIdx.x;
    int v = (i < n) ? g_cnt[i] : 0;
    sh[threadIdx.x] = v;
    __syncthreads();
    for (int off = 1; off < SCAN_B; off <<= 1) {
        int t = 0;
        if ((int)threadIdx.x >= off) t = sh[threadIdx.x - off];
        __syncthreads();
        if ((int)threadIdx.x >= off) sh[threadIdx.x] += t;
        __syncthreads();
    }
    if (i < n) g_rowstart[i] = sh[threadIdx.x];
    if (threadIdx.x == SCAN_B - 1) g_partials[blockIdx.x] = sh[SCAN_B - 1];
}

__global__ __launch_bounds__(256) void k_scan3(int n, int nb) {
    __shared__ int sp[128];
    int tid = threadIdx.x;
    if (tid < 128) sp[tid] = (tid < nb) ? g_partials[tid] : 0;
    __syncthreads();
    for (int off = 1; off < 128; off <<= 1) {
        int v = 0;
        if (tid < 128 && tid >= off) v = sp[tid - off];
        __syncthreads();
        if (tid < 128 && tid >= off) sp[tid] += v;
        __syncthreads();
    }
    int i = blockIdx.x * blockDim.x + tid;
    if (i < n) {
        int b = i / SCAN_B;
        int excl = (b == 0) ? 0 : sp[b - 1];
        int cnt  = g_cnt[i];
        int incl = g_rowstart[i] + excl;
        g_rowstart[i] = incl - cnt;
        if (i == n - 1) g_rowstart[n] = incl;
        g_dinv[i] = rsqrtf((float)cnt + 1.0f);
    }
}

// ---------------- bucketing: vectorized (e % 4 == 0) + scalar fallback ----------------
__global__ void k_bucket4(const void* __restrict__ ei, int e, int n) {
    int i = blockIdx.x * blockDim.x + threadIdx.x;
    int nv = e >> 2;
    if (i >= nv) return;
    int s0, s1, s2, s3, d0, d1, d2, d3;
    if (g_is64) {
        const long long* src = (const long long*)ei;
        const long long* dst = src + e;
        longlong2 sa = ((const longlong2*)src)[i * 2];
        longlong2 sb = ((const longlong2*)src)[i * 2 + 1];
        longlong2 da = ((const longlong2*)dst)[i * 2];
        longlong2 db = ((const longlong2*)dst)[i * 2 + 1];
        s0 = (int)sa.x; s1 = (int)sa.y; s2 = (int)sb.x; s3 = (int)sb.y;
        d0 = (int)da.x; d1 = (int)da.y; d2 = (int)db.x; d3 = (int)db.y;
    } else {
        const int* src = (const int*)ei;
        const int* dst = src + e;
        int4 sa = ((const int4*)src)[i];
        int4 da = ((const int4*)dst)[i];
        s0 = sa.x; s1 = sa.y; s2 = sa.z; s3 = sa.w;
        d0 = da.x; d1 = da.y; d2 = da.z; d3 = da.w;
    }
    if ((unsigned)d0 < (unsigned)n && (unsigned)s0 < (unsigned)n)
        g_src_sorted[g_rowstart[d0] + atomicAdd(&g_cursor[d0], 1)] = s0;
    if ((unsigned)d1 < (unsigned)n && (unsigned)s1 < (unsigned)n)
        g_src_sorted[g_rowstart[d1] + atomicAdd(&g_cursor[d1], 1)] = s1;
    if ((unsigned)d2 < (unsigned)n && (unsigned)s2 < (unsigned)n)
        g_src_sorted[g_rowstart[d2] + atomicAdd(&g_cursor[d2], 1)] = s2;
    if ((unsigned)d3 < (unsigned)n && (unsigned)s3 < (unsigned)n)
        g_src_sorted[g_rowstart[d3] + atomicAdd(&g_cursor[d3], 1)] = s3;
}

__global__ void k_bucket(const void* __restrict__ ei, int e, int n) {
    int i = blockIdx.x * blockDim.x + threadIdx.x;
    if (i < e) {
        int s = edge_at(ei, i);
        int d = edge_at(ei, (size_t)e + i);
        if ((unsigned)d < (unsigned)n && (unsigned)s < (unsigned)n) {
            int pos = atomicAdd(&g_cursor[d], 1);
            g_src_sorted[g_rowstart[d] + pos] = s;
        }
    }
}

// ---------------- Tensor-core GEMM (R8/R11 VERBATIM — register profile load-bearing) ----------------
#define GMB 128
#define GKB 32
#define GSTR 40

__device__ __forceinline__ void mma_bf16(
    float& c0, float& c1, float& c2, float& c3,
    unsigned a0, unsigned a1, unsigned a2, unsigned a3,
    unsigned b0, unsigned b1)
{
    asm volatile(
        "mma.sync.aligned.m16n8k16.row.col.f32.bf16.bf16.f32 "
        "{%0,%1,%2,%3}, {%4,%5,%6,%7}, {%8,%9}, {%0,%1,%2,%3};"
        : "+f"(c0), "+f"(c1), "+f"(c2), "+f"(c3)
        : "r"(a0), "r"(a1), "r"(a2), "r"(a3), "r"(b0), "r"(b1));
}

__device__ __forceinline__ __nv_bfloat162 split2(float a, float b, __nv_bfloat162& lo) {
    __nv_bfloat16 ha = __float2bfloat16_rn(a);
    __nv_bfloat16 hb = __float2bfloat16_rn(b);
    __nv_bfloat16 la = __float2bfloat16_rn(a - __bfloat162float(ha));
    __nv_bfloat16 lb = __float2bfloat16_rn(b - __bfloat162float(hb));
    lo = __halves2bfloat162(la, lb);
    return __halves2bfloat162(ha, hb);
}

__global__ __launch_bounds__(256) void k_gemm_tc(
    const float* __restrict__ Aext, int mode, int layer, int n)
{
    __shared__ __align__(16) __nv_bfloat16 Ah[GMB][GSTR];
    __shared__ __align__(16) __nv_bfloat16 Al[GMB][GSTR];
    __shared__ __align__(16) __nv_bfloat16 Wh[HID][GSTR];
    __shared__ __align__(16) __nv_bfloat16 Wl[HID][GSTR];

    int tid  = threadIdx.x;
    int warp = tid >> 5;
    int lane = tid & 31;
    int group = lane >> 2;
    int tig   = lane & 3;
    int wm = (warp >> 1) * 32;
    int wn = (warp & 1) * 64;
    int br = blockIdx.x * GMB;
    const float* A = mode ? (const float*)g_bufC : Aext;
    const __nv_bfloat16* GWh = g_Wh[layer];
    const __nv_bfloat16* GWl = g_Wl[layer];

    float acc[2][8][4];
#pragma unroll
    for (int mi = 0; mi < 2; mi++)
#pragma unroll
        for (int j = 0; j < 8; j++)
#pragma unroll
            for (int q = 0; q < 4; q++) acc[mi][j][q] = 0.f;

    for (int kb = 0; kb < HID; kb += GKB) {
#pragma unroll
        for (int u = 0; u < 4; u++) {
            int idx = tid + u * 256;
            int row = idx >> 3;
            int c4  = idx & 7;
            int gr  = br + row;
            float4 v = make_float4(0.f, 0.f, 0.f, 0.f);
            if (gr < n) v = ((const float4*)A)[(size_t)gr * 32 + (kb >> 2) + c4];
            if (mode) {
                float4 sc = ((const float4*)g_scale)[(kb >> 2) + c4];
                float4 sh = ((const float4*)g_shift)[(kb >> 2) + c4];
                v.x = fmaxf(fmaf(v.x, sc.x, sh.x), 0.f);
                v.y = fmaxf(fmaf(v.y, sc.y, sh.y), 0.f);
                v.z = fmaxf(fmaf(v.z, sc.z, sh.z), 0.f);
                v.w = fmaxf(fmaf(v.w, sc.w, sh.w), 0.f);
            }
            int kc = c4 * 4;
            __nv_bfloat162 lo0, lo1;
            __nv_bfloat162 hi0 = split2(v.x, v.y, lo0);
            __nv_bfloat162 hi1 = split2(v.z, v.w, lo1);
            *(__nv_bfloat162*)&Ah[row][kc]     = hi0;
            *(__nv_bfloat162*)&Ah[row][kc + 2] = hi1;
            *(__nv_bfloat162*)&Al[row][kc]     = lo0;
            *(__nv_bfloat162*)&Al[row][kc + 2] = lo1;
        }
#pragma unroll
        for (int u = 0; u < 2; u++) {
            int idx = tid + u * 256;
            int nr = idx >> 2;
            int q  = idx & 3;
            *(int4*)&Wh[nr][q * 8] = *(const int4*)&GWh[nr * HID + kb + q * 8];
            *(int4*)&Wl[nr][q * 8] = *(const int4*)&GWl[nr * HID + kb + q * 8];
        }
        __syncthreads();

#pragma unroll
        for (int ks = 0; ks < 2; ks++) {
            int k0 = ks * 16;
            int ac0 = k0 + tig * 2, ac1 = k0 + tig * 2 + 8;
            unsigned ah[2][4], al[2][4];
#pragma unroll
            for (int mi = 0; mi < 2; mi++) {
                int ar0 = wm + mi * 16 + group, ar1 = ar0 + 8;
                ah[mi][0] = *(const unsigned*)&Ah[ar0][ac0];
                ah[mi][1] = *(const unsigned*)&Ah[ar1][ac0];
                ah[mi][2] = *(const unsigned*)&Ah[ar0][ac1];
                ah[mi][3] = *(const unsigned*)&Ah[ar1][ac1];
                al[mi][0] = *(const unsigned*)&Al[ar0][ac0];
                al[mi][1] = *(const unsigned*)&Al[ar1][ac0];
                al[mi][2] = *(const unsigned*)&Al[ar0][ac1];
                al[mi][3] = *(const unsigned*)&Al[ar1][ac1];
            }
#pragma unroll
            for (int j = 0; j < 8; j++) {
                int nr = wn + j * 8 + group;
                unsigned bh0 = *(const unsigned*)&Wh[nr][ac0];
                unsigned bh1 = *(const unsigned*)&Wh[nr][ac1];
                unsigned bl0 = *(const unsigned*)&Wl[nr][ac0];
                unsigned bl1 = *(const unsigned*)&Wl[nr][ac1];
#pragma unroll
                for (int mi = 0; mi < 2; mi++) {
                    mma_bf16(acc[mi][j][0], acc[mi][j][1], acc[mi][j][2], acc[mi][j][3],
                             ah[mi][0], ah[mi][1], ah[mi][2], ah[mi][3], bh0, bh1);
                    mma_bf16(acc[mi][j][0], acc[mi][j][1], acc[mi][j][2], acc[mi][j][3],
                             ah[mi][0], ah[mi][1], ah[mi][2], ah[mi][3], bl0, bl1);
                    mma_bf16(acc[mi][j][0], acc[mi][j][1], acc[mi][j][2], acc[mi][j][3],
                             al[mi][0], al[mi][1], al[mi][2], al[mi][3], bh0, bh1);
                }
            }
        }
        __syncthreads();
    }
#pragma unroll
    for (int mi = 0; mi < 2; mi++) {
        int row0 = br + wm + mi * 16 + group;
        int row1 = row0 + 8;
        float d0 = (row0 < n) ? g_dinv[row0] : 0.f;
        float d1 = (row1 < n) ? g_dinv[row1] : 0.f;
#pragma unroll
        for (int j = 0; j < 8; j++) {
            int col = wn + j * 8 + tig * 2;
            if (row0 < n) *(float2*)&g_bufB[(size_t)row0 * HID + col]
                = make_float2(d0 * acc[mi][j][0], d0 * acc[mi][j][1]);
            if (row1 < n) *(float2*)&g_bufB[(size_t)row1 * HID + col]
                = make_float2(d1 * acc[mi][j][2], d1 * acc[mi][j][3]);
        }
    }
}

// ---------------- small GEMM: msg10 = dinv * (relu(bn(g_bufC)) @ W2) -> g_bufB[n,10] ----------------
__global__ __launch_bounds__(256) void k_gemm10(
    const float* __restrict__ W, int n)
{
    __shared__ float Ws[HID * NOUT];
    int tid = threadIdx.x;
    for (int i = tid; i < HID * NOUT; i += blockDim.x) Ws[i] = W[i];
    __syncthreads();
    int warp = tid >> 5, lane = tid & 31;
    int row = blockIdx.x * (blockDim.x >> 5) + warp;
    if (row >= n) return;
    const float* A = (const float*)g_bufC;
    float a0 = fmaxf(fmaf(A[(size_t)row * HID + lane],      g_scale[lane],      g_shift[lane]),      0.f);
    float a1 = fmaxf(fmaf(A[(size_t)row * HID + 32 + lane], g_scale[lane + 32], g_shift[lane + 32]), 0.f);
    float a2 = fmaxf(fmaf(A[(size_t)row * HID + 64 + lane], g_scale[lane + 64], g_shift[lane + 64]), 0.f);
    float a3 = fmaxf(fmaf(A[(size_t)row * HID + 96 + lane], g_scale[lane + 96], g_shift[lane + 96]), 0.f);
    float di = g_dinv[row];
#pragma unroll
    for (int c = 0; c < NOUT; c++) {
        float p = a0 * Ws[lane * NOUT + c]
                + a1 * Ws[(lane + 32) * NOUT + c]
                + a2 * Ws[(lane + 64) * NOUT + c]
                + a3 * Ws[(lane + 96) * NOUT + c];
#pragma unroll
        for (int off = 16; off > 0; off >>= 1)
            p += __shfl_down_sync(0xffffffffu, p, off);
        if (lane == 0) g_bufB[(size_t)row * NOUT + c] = di * p;
    }
}

// ---------------- aggregation + fused BN stats, width 128 ----------------
// LATENCY FIX (R14 profile: issue 33%, L2 49% -> latency-bound, not BW-bound):
// software-pipelined index prefetch breaks the idx->msg 2-hop dependency chain;
// dual accumulators halve the dependent-FADD chain.
__global__ __launch_bounds__(256) void k_agg128(
    const float* __restrict__ bias, int n, int layer)
{
    __shared__ float shs[8][HID];
    __shared__ float shq[8][HID];
    int ty = threadIdx.y;
    int lane = threadIdx.x;
    int node = blockIdx.x * 8 + ty;
    bool active = node < n;
    const float4* hp = (const float4*)g_bufB;

    float4 o = make_float4(0.f, 0.f, 0.f, 0.f);
    if (active) {
        float di = g_dinv[node];
        float4 a0 = hp[(size_t)node * 32 + lane];       // msg[node] (self-loop)
        float4 a1 = make_float4(0.f, 0.f, 0.f, 0.f);
        int beg = g_rowstart[node], end = g_rowstart[node + 1];
        int j = beg;
        int i0 = 0, i1 = 0, i2 = 0, i3 = 0;
        bool have = (j + 3 < end);
        if (have) {
            i0 = g_src_sorted[j];     i1 = g_src_sorted[j + 1];
            i2 = g_src_sorted[j + 2]; i3 = g_src_sorted[j + 3];
        }
        while (have) {
            int jn = j + 4;
            int t0 = 0, t1 = 0, t2 = 0, t3 = 0;
            bool more = (jn + 3 < end);
            if (more) {               // prefetch next group's indices NOW
                t0 = g_src_sorted[jn];     t1 = g_src_sorted[jn + 1];
                t2 = g_src_sorted[jn + 2]; t3 = g_src_sorted[jn + 3];
            }
            float4 m0 = hp[(size_t)i0 * 32 + lane];
            float4 m1 = hp[(size_t)i1 * 32 + lane];
            float4 m2 = hp[(size_t)i2 * 32 + lane];
            float4 m3 = hp[(size_t)i3 * 32 + lane];
            a0.x += m0.x + m1.x; a0.y += m0.y + m1.y;
            a0.z += m0.z + m1.z; a0.w += m0.w + m1.w;
            a1.x += m2.x + m3.x; a1.y += m2.y + m3.y;
            a1.z += m2.z + m3.z; a1.w += m2.w + m3.w;
            i0 = t0; i1 = t1; i2 = t2; i3 = t3;
            j = jn;
            have = more;
        }
        for (; j < end; j++) {
            int s = g_src_sorted[j];
            float4 m = hp[(size_t)s * 32 + lane];
            a0.x += m.x; a0.y += m.y; a0.z += m.z; a0.w += m.w;
        }
        a0.x += a1.x; a0.y += a1.y; a0.z += a1.z; a0.w += a1.w;
        float4 bb = ((const float4*)bias)[lane];
        o.x = fmaf(di, a0.x, bb.x); o.y = fmaf(di, a0.y, bb.y);
        o.z = fmaf(di, a0.z, bb.z); o.w = fmaf(di, a0.w, bb.w);
        ((float4*)g_bufC)[(size_t)node * 32 + lane] = o;
    }

    *(float4*)&shs[ty][lane * 4] = o;
    *(float4*)&shq[ty][lane * 4] = make_float4(o.x * o.x, o.y * o.y, o.z * o.z, o.w * o.w);
    __syncthreads();
    int tid = ty * 32 + lane;
    if (tid < HID) {
        float s = 0.f, q = 0.f;
#pragma unroll
        for (int r = 0; r < 8; r++) { s += shs[r][tid]; q += shq[r][tid]; }
        atomicAdd(&g_cs[layer][tid], s);
        atomicAdd(&g_cq[layer][tid], q);
    }
}

// width-10 final agg: two edges per iteration (lane halves) + index prefetch
__global__ __launch_bounds__(256) void k_agg10(
    const float* __restrict__ bias, float* __restrict__ out, int n)
{
    int ty = threadIdx.y;
    int lane = threadIdx.x;
    int node = blockIdx.x * 8 + ty;
    if (node >= n) return;
    int half = lane >> 4;
    int c = lane & 15;
    const float* h = (const float*)g_bufB;
    float di = g_dinv[node];
    float acc = 0.f;
    if (half == 0 && c < NOUT) acc = h[(size_t)node * NOUT + c];
    int beg = g_rowstart[node], end = g_rowstart[node + 1];
    int j = beg + half;
    int s = 0;
    bool have = (j < end);
    if (have) s = g_src_sorted[j];
    while (have) {
        int jn = j + 2;
        int sn = 0;
        bool more = (jn < end);
        if (more) sn = g_src_sorted[jn];
        if (c < NOUT) acc += h[(size_t)s * NOUT + c];
        s = sn; j = jn; have = more;
    }
    acc += __shfl_xor_sync(0xffffffffu, acc, 16);
    if (half == 0 && c < NOUT)
        out[(size_t)node * NOUT + c] = fmaf(di, acc, bias[c]);
}

// ---------------- BN finalize (standalone — fusing into hot kernels regresses, R9/R13) ----------------
__global__ __launch_bounds__(128) void k_bnfinal(
    const float* __restrict__ g, const float* __restrict__ be,
    int layer, int n)
{
    int c = threadIdx.x;
    float inv_n = 1.0f / (float)n;
    float mu  = g_cs[layer][c] * inv_n;
    float var = fmaxf(g_cq[layer][c] * inv_n - mu * mu, 0.0f);
    float sc = g[c] * rsqrtf(var + BN_EPS);
    g_scale[c] = sc;
    g_shift[c] = fmaf(-mu, sc, be[c]);
}

// ---------------- host launcher: kernel launches ONLY ----------------
extern "C" void kernel_launch(void* const* d_in, const int* in_sizes, int n_in,
                              void* d_out, int out_size)
{
    const float* x  = (const float*)d_in[0];
    const void*  ei = d_in[1];
    const float* W0 = (const float*)d_in[2];  const float* b0 = (const float*)d_in[3];
    const float* g0 = (const float*)d_in[4];  const float* be0 = (const float*)d_in[5];
    const float* W1 = (const float*)d_in[6];  const float* b1 = (const float*)d_in[7];
    const float* g1 = (const float*)d_in[8];  const float* be1 = (const float*)d_in[9];
    const float* W2 = (const float*)d_in[10]; const float* b2 = (const float*)d_in[11];

    int n = in_sizes[0] / HID;
    int e = in_sizes[1] / 2;
    float* out = (float*)d_out;

    int nb_n256 = (n + 255) / 256;
    int nb_scan = (n + SCAN_B - 1) / SCAN_B;

    // ---- init + CSR build (R12-style multi-kernel; one-kernel variant cost +4us) ----
    k_init<<<nb_n256, 256>>>((const unsigned int*)ei, W0, W1, n);
    if ((e & 3) == 0) {
        int nb_v = ((e >> 2) + 255) / 256;
        k_count4<<<nb_v, 256>>>(ei, e, n);
        k_scan1<<<nb_scan, SCAN_B>>>(n);
        k_scan3<<<nb_n256, 256>>>(n, nb_scan);
        k_bucket4<<<nb_v, 256>>>(ei, e, n);
    } else {
        int nb_e256 = (e + 255) / 256;
        k_count<<<nb_e256, 256>>>(ei, e, n);
        k_scan1<<<nb_scan, SCAN_B>>>(n);
        k_scan3<<<nb_n256, 256>>>(n, nb_scan);
        k_bucket<<<nb_e256, 256>>>(ei, e, n);
    }

    dim3 aggBlk(32, 8);
    int aggGrid = (n + 7) / 8;
    int gemmGrid = (n + GMB - 1) / GMB;

    // ---- layer 0 ----
    k_gemm_tc<<<gemmGrid, 256>>>(x, 0, 0, n);
    k_agg128<<<aggGrid, aggBlk>>>(b0, n, 0);
    k_bnfinal<<<1, 128>>>(g0, be0, 0, n);

    // ---- layer 1 (BN0 apply fused into A-load) ----
    k_gemm_tc<<<gemmGrid, 256>>>(x, 1, 1, n);
    k_agg128<<<aggGrid, aggBlk>>>(b1, n, 1);
    k_bnfinal<<<1, 128>>>(g1, be1, 1, n);

    // ---- layer 2 (BN1 apply fused into A-load; output) ----
    k_gemm10<<<(n + 7) / 8, 256>>>(W2, n);
    k_agg10<<<aggGrid, aggBlk>>>(b2, out, n);
}

// round 16
// speedup vs baseline: 1.1333x; 1.0239x over previous
#include <cuda_runtime.h>
#include <cuda_bf16.h>
#include <math.h>

// ---------------- problem constants (match dataset) ----------------
#define NMAXN 100000
#define EMAXE 1600000
#define HID 128
#define NOUT 10
#define BN_EPS 1e-5f
#define SCAN_B 1024

// ---------------- static device scratch (alloc-free rule) ----------------
__device__ __align__(256) float g_bufB[(size_t)NMAXN * HID]; // gemm output (msg)
__device__ __align__(256) float g_bufC[(size_t)NMAXN * HID]; // aggregation output
__device__ __align__(256) int   g_cnt[NMAXN];
__device__ __align__(256) int   g_rowstart[NMAXN + 1];
__device__ __align__(256) int   g_cursor[NMAXN];
__device__ __align__(256) int   g_src_sorted[EMAXE];
__device__ __align__(256) float g_dinv[NMAXN];
__device__ __align__(256) float g_cs[2][HID];
__device__ __align__(256) float g_cq[2][HID];
__device__ __align__(256) float g_scale[HID];
__device__ __align__(256) float g_shift[HID];
__device__ __align__(256) int   g_partials[128];
__device__ __align__(256) __nv_bfloat16 g_Wh[2][HID * HID];
__device__ __align__(256) __nv_bfloat16 g_Wl[2][HID * HID];
__device__ int g_is64;

__device__ __forceinline__ int edge_at(const void* ei, size_t idx) {
    if (g_is64) return (int)((const long long*)ei)[idx];
    return ((const int*)ei)[idx];
}

// ---------------- fused init: zero + dtype detect + W split (both layers) ----------------
__global__ void k_init(const unsigned int* __restrict__ raw,
                       const float* __restrict__ W0, const float* __restrict__ W1,
                       int n)
{
    int i = blockIdx.x * blockDim.x + threadIdx.x;
    if (i < n) { g_cnt[i] = 0; g_cursor[i] = 0; }
    if (i < HID) {
        g_cs[0][i] = 0.f; g_cq[0][i] = 0.f;
        g_cs[1][i] = 0.f; g_cq[1][i] = 0.f;
    }
    if (i < 2 * HID * HID) {
        int layer = i >> 14;
        int r = i & 16383;
        int k = r >> 7, nn = r & 127;
        float v = (layer ? W1 : W0)[r];
        __nv_bfloat16 h = __float2bfloat16_rn(v);
        __nv_bfloat16 l = __float2bfloat16_rn(v - __bfloat162float(h));
        g_Wh[layer][nn * HID + k] = h;
        g_Wl[layer][nn * HID + k] = l;
    }
    if (blockIdx.x == 0) {
        __shared__ int any;
        if (threadIdx.x == 0) any = 0;
        __syncthreads();
        unsigned int w = raw[threadIdx.x * 2 + 1];
        if (w != 0u) atomicOr(&any, 1);
        __syncthreads();
        if (threadIdx.x == 0) g_is64 = any ? 0 : 1;
    }
}

// ---------------- edge counting ----------------
__global__ void k_count4(const void* __restrict__ ei, int e, int n) {
    int i = blockIdx.x * blockDim.x + threadIdx.x;
    int nv = e >> 2;
    if (i >= nv) return;
    int d0, d1, d2, d3;
    if (g_is64) {
        const long long* dst = (const long long*)ei + e;
        longlong2 a = ((const longlong2*)dst)[i * 2];
        longlong2 b = ((const longlong2*)dst)[i * 2 + 1];
        d0 = (int)a.x; d1 = (int)a.y; d2 = (int)b.x; d3 = (int)b.y;
    } else {
        const int* dst = (const int*)ei + e;
        int4 a = ((const int4*)dst)[i];
        d0 = a.x; d1 = a.y; d2 = a.z; d3 = a.w;
    }
    if ((unsigned)d0 < (unsigned)n) atomicAdd(&g_cnt[d0], 1);
    if ((unsigned)d1 < (unsigned)n) atomicAdd(&g_cnt[d1], 1);
    if ((unsigned)d2 < (unsigned)n) atomicAdd(&g_cnt[d2], 1);
    if ((unsigned)d3 < (unsigned)n) atomicAdd(&g_cnt[d3], 1);
}

__global__ void k_count(const void* __restrict__ ei, int e, int n) {
    int i = blockIdx.x * blockDim.x + threadIdx.x;
    if (i < e) {
        int d = edge_at(ei, (size_t)e + i);
        if ((unsigned)d < (unsigned)n) atomicAdd(&g_cnt[d], 1);
    }
}

// ---------------- scan ----------------
__global__ void k_scan1(int n) {
    __shared__ int sh[SCAN_B];
    int i = blockIdx.x * SCAN_B + threadIdx.x;
    int v = (i < n) ? g_cnt[i] : 0;
    sh[threadIdx.x] = v;
    __syncthreads();
    for (int off = 1; off < SCAN_B; off <<= 1) {
        int t = 0;
        if ((int)threadIdx.x >= off) t = sh[threadIdx.x - off];
        __syncthreads();
        if ((int)threadIdx.x >= off) sh[threadIdx.x] += t;
        __syncthreads();
    }
    if (i < n) g_rowstart[i] = sh[threadIdx.x];
    if (threadIdx.x == SCAN_B - 1) g_partials[blockIdx.x] = sh[SCAN_B - 1];
}

__global__ __launch_bounds__(256) void k_scan3(int n, int nb) {
    __shared__ int sp[128];
    int tid = threadIdx.x;
    if (tid < 128) sp[tid] = (tid < nb) ? g_partials[tid] : 0;
    __syncthreads();
    for (int off = 1; off < 128; off <<= 1) {
        int v = 0;
        if (tid < 128 && tid >= off) v = sp[tid - off];
        __syncthreads();
        if (tid < 128 && tid >= off) sp[tid] += v;
        __syncthreads();
    }
    int i = blockIdx.x * blockDim.x + tid;
    if (i < n) {
        int b = i / SCAN_B;
        int excl = (b == 0) ? 0 : sp[b - 1];
        int cnt  = g_cnt[i];
        int incl = g_rowstart[i] + excl;
        g_rowstart[i] = incl - cnt;
        if (i == n - 1) g_rowstart[n] = incl;
        g_dinv[i] = rsqrtf((float)cnt + 1.0f);
    }
}

// ---------------- bucketing ----------------
__global__ void k_bucket4(const void* __restrict__ ei, int e, int n) {
    int i = blockIdx.x * blockDim.x + threadIdx.x;
    int nv = e >> 2;
    if (i >= nv) return;
    int s0, s1, s2, s3, d0, d1, d2, d3;
    if (g_is64) {
        const long long* src = (const long long*)ei;
        const long long* dst = src + e;
        longlong2 sa = ((const longlong2*)src)[i * 2];
        longlong2 sb = ((const longlong2*)src)[i * 2 + 1];
        longlong2 da = ((const longlong2*)dst)[i * 2];
        longlong2 db = ((const longlong2*)dst)[i * 2 + 1];
        s0 = (int)sa.x; s1 = (int)sa.y; s2 = (int)sb.x; s3 = (int)sb.y;
        d0 = (int)da.x; d1 = (int)da.y; d2 = (int)db.x; d3 = (int)db.y;
    } else {
        const int* src = (const int*)ei;
        const int* dst = src + e;
        int4 sa = ((const int4*)src)[i];
        int4 da = ((const int4*)dst)[i];
        s0 = sa.x; s1 = sa.y; s2 = sa.z; s3 = sa.w;
        d0 = da.x; d1 = da.y; d2 = da.z; d3 = da.w;
    }
    if ((unsigned)d0 < (unsigned)n && (unsigned)s0 < (unsigned)n)
        g_src_sorted[g_rowstart[d0] + atomicAdd(&g_cursor[d0], 1)] = s0;
    if ((unsigned)d1 < (unsigned)n && (unsigned)s1 < (unsigned)n)
        g_src_sorted[g_rowstart[d1] + atomicAdd(&g_cursor[d1], 1)] = s1;
    if ((unsigned)d2 < (unsigned)n && (unsigned)s2 < (unsigned)n)
        g_src_sorted[g_rowstart[d2] + atomicAdd(&g_cursor[d2], 1)] = s2;
    if ((unsigned)d3 < (unsigned)n && (unsigned)s3 < (unsigned)n)
        g_src_sorted[g_rowstart[d3] + atomicAdd(&g_cursor[d3], 1)] = s3;
}

__global__ void k_bucket(const void* __restrict__ ei, int e, int n) {
    int i = blockIdx.x * blockDim.x + threadIdx.x;
    if (i < e) {
        int s = edge_at(ei, i);
        int d = edge_at(ei, (size_t)e + i);
        if ((unsigned)d < (unsigned)n && (unsigned)s < (unsigned)n) {
            int pos = atomicAdd(&g_cursor[d], 1);
            g_src_sorted[g_rowstart[d] + pos] = s;
        }
    }
}

// ---------------- Tensor-core GEMM (epilogue flag only; core R8/R11 verbatim) ----------------
// scaleOut=1: store dinv[row]*C (pre-scaled msg). scaleOut=0: store raw C
// (layer 0 runs BEFORE the CSR build so dinv isn't available yet).
#define GMB 128
#define GKB 32
#define GSTR 40

__device__ __forceinline__ void mma_bf16(
    float& c0, float& c1, float& c2, float& c3,
    unsigned a0, unsigned a1, unsigned a2, unsigned a3,
    unsigned b0, unsigned b1)
{
    asm volatile(
        "mma.sync.aligned.m16n8k16.row.col.f32.bf16.bf16.f32 "
        "{%0,%1,%2,%3}, {%4,%5,%6,%7}, {%8,%9}, {%0,%1,%2,%3};"
        : "+f"(c0), "+f"(c1), "+f"(c2), "+f"(c3)
        : "r"(a0), "r"(a1), "r"(a2), "r"(a3), "r"(b0), "r"(b1));
}

__device__ __forceinline__ __nv_bfloat162 split2(float a, float b, __nv_bfloat162& lo) {
    __nv_bfloat16 ha = __float2bfloat16_rn(a);
    __nv_bfloat16 hb = __float2bfloat16_rn(b);
    __nv_bfloat16 la = __float2bfloat16_rn(a - __bfloat162float(ha));
    __nv_bfloat16 lb = __float2bfloat16_rn(b - __bfloat162float(hb));
    lo = __halves2bfloat162(la, lb);
    return __halves2bfloat162(ha, hb);
}

__global__ __launch_bounds__(256) void k_gemm_tc(
    const float* __restrict__ Aext, int mode, int layer, int scaleOut, int n)
{
    __shared__ __align__(16) __nv_bfloat16 Ah[GMB][GSTR];
    __shared__ __align__(16) __nv_bfloat16 Al[GMB][GSTR];
    __shared__ __align__(16) __nv_bfloat16 Wh[HID][GSTR];
    __shared__ __align__(16) __nv_bfloat16 Wl[HID][GSTR];

    int tid  = threadIdx.x;
    int warp = tid >> 5;
    int lane = tid & 31;
    int group = lane >> 2;
    int tig   = lane & 3;
    int wm = (warp >> 1) * 32;
    int wn = (warp & 1) * 64;
    int br = blockIdx.x * GMB;
    const float* A = mode ? (const float*)g_bufC : Aext;
    const __nv_bfloat16* GWh = g_Wh[layer];
    const __nv_bfloat16* GWl = g_Wl[layer];

    float acc[2][8][4];
#pragma unroll
    for (int mi = 0; mi < 2; mi++)
#pragma unroll
        for (int j = 0; j < 8; j++)
#pragma unroll
            for (int q = 0; q < 4; q++) acc[mi][j][q] = 0.f;

    for (int kb = 0; kb < HID; kb += GKB) {
#pragma unroll
        for (int u = 0; u < 4; u++) {
            int idx = tid + u * 256;
            int row = idx >> 3;
            int c4  = idx & 7;
            int gr  = br + row;
            float4 v = make_float4(0.f, 0.f, 0.f, 0.f);
            if (gr < n) v = ((const float4*)A)[(size_t)gr * 32 + (kb >> 2) + c4];
            if (mode) {
                float4 sc = ((const float4*)g_scale)[(kb >> 2) + c4];
                float4 sh = ((const float4*)g_shift)[(kb >> 2) + c4];
                v.x = fmaxf(fmaf(v.x, sc.x, sh.x), 0.f);
                v.y = fmaxf(fmaf(v.y, sc.y, sh.y), 0.f);
                v.z = fmaxf(fmaf(v.z, sc.z, sh.z), 0.f);
                v.w = fmaxf(fmaf(v.w, sc.w, sh.w), 0.f);
            }
            int kc = c4 * 4;
            __nv_bfloat162 lo0, lo1;
            __nv_bfloat162 hi0 = split2(v.x, v.y, lo0);
            __nv_bfloat162 hi1 = split2(v.z, v.w, lo1);
            *(__nv_bfloat162*)&Ah[row][kc]     = hi0;
            *(__nv_bfloat162*)&Ah[row][kc + 2] = hi1;
            *(__nv_bfloat162*)&Al[row][kc]     = lo0;
            *(__nv_bfloat162*)&Al[row][kc + 2] = lo1;
        }
#pragma unroll
        for (int u = 0; u < 2; u++) {
            int idx = tid + u * 256;
            int nr = idx >> 2;
            int q  = idx & 3;
            *(int4*)&Wh[nr][q * 8] = *(const int4*)&GWh[nr * HID + kb + q * 8];
            *(int4*)&Wl[nr][q * 8] = *(const int4*)&GWl[nr * HID + kb + q * 8];
        }
        __syncthreads();

#pragma unroll
        for (int ks = 0; ks < 2; ks++) {
            int k0 = ks * 16;
            int ac0 = k0 + tig * 2, ac1 = k0 + tig * 2 + 8;
            unsigned ah[2][4], al[2][4];
#pragma unroll
            for (int mi = 0; mi < 2; mi++) {
                int ar0 = wm + mi * 16 + group, ar1 = ar0 + 8;
                ah[mi][0] = *(const unsigned*)&Ah[ar0][ac0];
                ah[mi][1] = *(const unsigned*)&Ah[ar1][ac0];
                ah[mi][2] = *(const unsigned*)&Ah[ar0][ac1];
                ah[mi][3] = *(const unsigned*)&Ah[ar1][ac1];
                al[mi][0] = *(const unsigned*)&Al[ar0][ac0];
                al[mi][1] = *(const unsigned*)&Al[ar1][ac0];
                al[mi][2] = *(const unsigned*)&Al[ar0][ac1];
                al[mi][3] = *(const unsigned*)&Al[ar1][ac1];
            }
#pragma unroll
            for (int j = 0; j < 8; j++) {
                int nr = wn + j * 8 + group;
                unsigned bh0 = *(const unsigned*)&Wh[nr][ac0];
                unsigned bh1 = *(const unsigned*)&Wh[nr][ac1];
                unsigned bl0 = *(const unsigned*)&Wl[nr][ac0];
                unsigned bl1 = *(const unsigned*)&Wl[nr][ac1];
#pragma unroll
                for (int mi = 0; mi < 2; mi++) {
                    mma_bf16(acc[mi][j][0], acc[mi][j][1], acc[mi][j][2], acc[mi][j][3],
                             ah[mi][0], ah[mi][1], ah[mi][2], ah[mi][3], bh0, bh1);
                    mma_bf16(acc[mi][j][0], acc[mi][j][1], acc[mi][j][2], acc[mi][j][3],
                             ah[mi][0], ah[mi][1], ah[mi][2], ah[mi][3], bl0, bl1);
                    mma_bf16(acc[mi][j][0], acc[mi][j][1], acc[mi][j][2], acc[mi][j][3],
                             al[mi][0], al[mi][1], al[mi][2], al[mi][3], bh0, bh1);
                }
            }
        }
        __syncthreads();
    }
#pragma unroll
    for (int mi = 0; mi < 2; mi++) {
        int row0 = br + wm + mi * 16 + group;
        int row1 = row0 + 8;
        float d0 = (row0 < n) ? (scaleOut ? g_dinv[row0] : 1.f) : 0.f;
        float d1 = (row1 < n) ? (scaleOut ? g_dinv[row1] : 1.f) : 0.f;
#pragma unroll
        for (int j = 0; j < 8; j++) {
            int col = wn + j * 8 + tig * 2;
            if (row0 < n) *(float2*)&g_bufB[(size_t)row0 * HID + col]
                = make_float2(d0 * acc[mi][j][0], d0 * acc[mi][j][1]);
            if (row1 < n) *(float2*)&g_bufB[(size_t)row1 * HID + col]
                = make_float2(d1 * acc[mi][j][2], d1 * acc[mi][j][3]);
        }
    }
}

// ---------------- small GEMM ----------------
__global__ __launch_bounds__(256) void k_gemm10(
    const float* __restrict__ W, int n)
{
    __shared__ float Ws[HID * NOUT];
    int tid = threadIdx.x;
    for (int i = tid; i < HID * NOUT; i += blockDim.x) Ws[i] = W[i];
    __syncthreads();
    int warp = tid >> 5, lane = tid & 31;
    int row = blockIdx.x * (blockDim.x >> 5) + warp;
    if (row >= n) return;
    const float* A = (const float*)g_bufC;
    float a0 = fmaxf(fmaf(A[(size_t)row * HID + lane],      g_scale[lane],      g_shift[lane]),      0.f);
    float a1 = fmaxf(fmaf(A[(size_t)row * HID + 32 + lane], g_scale[lane + 32], g_shift[lane + 32]), 0.f);
    float a2 = fmaxf(fmaf(A[(size_t)row * HID + 64 + lane], g_scale[lane + 64], g_shift[lane + 64]), 0.f);
    float a3 = fmaxf(fmaf(A[(size_t)row * HID + 96 + lane], g_scale[lane + 96], g_shift[lane + 96]), 0.f);
    float di = g_dinv[row];
#pragma unroll
    for (int c = 0; c < NOUT; c++) {
        float p = a0 * Ws[lane * NOUT + c]
                + a1 * Ws[(lane + 32) * NOUT + c]
                + a2 * Ws[(lane + 64) * NOUT + c]
                + a3 * Ws[(lane + 96) * NOUT + c];
#pragma unroll
        for (int off = 16; off > 0; off >>= 1)
            p += __shfl_down_sync(0xffffffffu, p, off);
        if (lane == 0) g_bufB[(size_t)row * NOUT + c] = di * p;
    }
}

// ---------------- agg (pre-scaled msgs, layer 1) — R15 pipelined version ----------------
__global__ __launch_bounds__(256) void k_agg128(
    const float* __restrict__ bias, int n, int layer)
{
    __shared__ float shs[8][HID];
    __shared__ float shq[8][HID];
    int ty = threadIdx.y;
    int lane = threadIdx.x;
    int node = blockIdx.x * 8 + ty;
    bool active = node < n;
    const float4* hp = (const float4*)g_bufB;

    float4 o = make_float4(0.f, 0.f, 0.f, 0.f);
    if (active) {
        float di = g_dinv[node];
        float4 a0 = hp[(size_t)node * 32 + lane];
        float4 a1 = make_float4(0.f, 0.f, 0.f, 0.f);
        int beg = g_rowstart[node], end = g_rowstart[node + 1];
        int j = beg;
        int i0 = 0, i1 = 0, i2 = 0, i3 = 0;
        bool have = (j + 3 < end);
        if (have) {
            i0 = g_src_sorted[j];     i1 = g_src_sorted[j + 1];
            i2 = g_src_sorted[j + 2]; i3 = g_src_sorted[j + 3];
        }
        while (have) {
            int jn = j + 4;
            int t0 = 0, t1 = 0, t2 = 0, t3 = 0;
            bool more = (jn + 3 < end);
            if (more) {
                t0 = g_src_sorted[jn];     t1 = g_src_sorted[jn + 1];
                t2 = g_src_sorted[jn + 2]; t3 = g_src_sorted[jn + 3];
            }
            float4 m0 = hp[(size_t)i0 * 32 + lane];
            float4 m1 = hp[(size_t)i1 * 32 + lane];
            float4 m2 = hp[(size_t)i2 * 32 + lane];
            float4 m3 = hp[(size_t)i3 * 32 + lane];
            a0.x += m0.x + m1.x; a0.y += m0.y + m1.y;
            a0.z += m0.z + m1.z; a0.w += m0.w + m1.w;
            a1.x += m2.x + m3.x; a1.y += m2.y + m3.y;
            a1.z += m2.z + m3.z; a1.w += m2.w + m3.w;
            i0 = t0; i1 = t1; i2 = t2; i3 = t3;
            j = jn;
            have = more;
        }
        for (; j < end; j++) {
            int s = g_src_sorted[j];
            float4 m = hp[(size_t)s * 32 + lane];
            a0.x += m.x; a0.y += m.y; a0.z += m.z; a0.w += m.w;
        }
        a0.x += a1.x; a0.y += a1.y; a0.z += a1.z; a0.w += a1.w;
        float4 bb = ((const float4*)bias)[lane];
        o.x = fmaf(di, a0.x, bb.x); o.y = fmaf(di, a0.y, bb.y);
        o.z = fmaf(di, a0.z, bb.z); o.w = fmaf(di, a0.w, bb.w);
        ((float4*)g_bufC)[(size_t)node * 32 + lane] = o;
    }

    *(float4*)&shs[ty][lane * 4] = o;
    *(float4*)&shq[ty][lane * 4] = make_float4(o.x * o.x, o.y * o.y, o.z * o.z, o.w * o.w);
    __syncthreads();
    int tid = ty * 32 + lane;
    if (tid < HID) {
        float s = 0.f, q = 0.f;
#pragma unroll
        for (int r = 0; r < 8; r++) { s += shs[r][tid]; q += shq[r][tid]; }
        atomicAdd(&g_cs[layer][tid], s);
        atomicAdd(&g_cq[layer][tid], q);
    }
}

// ---------------- agg with per-edge dinv weights (layer 0; msgs unscaled) ----------------
// out[i] = dinv[i] * ( sum_e dinv[src]*h[src] + dinv[i]*h[i] ) + bias
__global__ __launch_bounds__(256) void k_agg128w(
    const float* __restrict__ bias, int n, int layer)
{
    __shared__ float shs[8][HID];
    __shared__ float shq[8][HID];
    int ty = threadIdx.y;
    int lane = threadIdx.x;
    int node = blockIdx.x * 8 + ty;
    bool active = node < n;
    const float4* hp = (const float4*)g_bufB;

    float4 o = make_float4(0.f, 0.f, 0.f, 0.f);
    if (active) {
        float di = g_dinv[node];
        float4 v = hp[(size_t)node * 32 + lane];
        float4 a0, a1;
        a0.x = di * v.x; a0.y = di * v.y; a0.z = di * v.z; a0.w = di * v.w;
        a1 = make_float4(0.f, 0.f, 0.f, 0.f);
        int beg = g_rowstart[node], end = g_rowstart[node + 1];
        int j = beg;
        int i0 = 0, i1 = 0, i2 = 0, i3 = 0;
        bool have = (j + 3 < end);
        if (have) {
            i0 = g_src_sorted[j];     i1 = g_src_sorted[j + 1];
            i2 = g_src_sorted[j + 2]; i3 = g_src_sorted[j + 3];
        }
        while (have) {
            int jn = j + 4;
            int t0 = 0, t1 = 0, t2 = 0, t3 = 0;
            bool more = (jn + 3 < end);
            if (more) {
                t0 = g_src_sorted[jn];     t1 = g_src_sorted[jn + 1];
                t2 = g_src_sorted[jn + 2]; t3 = g_src_sorted[jn + 3];
            }
            float w0 = g_dinv[i0], w1 = g_dinv[i1];
            float w2 = g_dinv[i2], w3 = g_dinv[i3];
            float4 m0 = hp[(size_t)i0 * 32 + lane];
            float4 m1 = hp[(size_t)i1 * 32 + lane];
            float4 m2 = hp[(size_t)i2 * 32 + lane];
            float4 m3 = hp[(size_t)i3 * 32 + lane];
            a0.x += w0 * m0.x + w1 * m1.x; a0.y += w0 * m0.y + w1 * m1.y;
            a0.z += w0 * m0.z + w1 * m1.z; a0.w += w0 * m0.w + w1 * m1.w;
            a1.x += w2 * m2.x + w3 * m3.x; a1.y += w2 * m2.y + w3 * m3.y;
            a1.z += w2 * m2.z + w3 * m3.z; a1.w += w2 * m2.w + w3 * m3.w;
            i0 = t0; i1 = t1; i2 = t2; i3 = t3;
            j = jn;
            have = more;
        }
        for (; j < end; j++) {
            int s = g_src_sorted[j];
            float w = g_dinv[s];
            float4 m = hp[(size_t)s * 32 + lane];
            a0.x += w * m.x; a0.y += w * m.y; a0.z += w * m.z; a0.w += w * m.w;
        }
        a0.x += a1.x; a0.y += a1.y; a0.z += a1.z; a0.w += a1.w;
        float4 bb = ((const float4*)bias)[lane];
        o.x = fmaf(di, a0.x, bb.x); o.y = fmaf(di, a0.y, bb.y);
        o.z = fmaf(di, a0.z, bb.z); o.w = fmaf(di, a0.w, bb.w);
        ((float4*)g_bufC)[(size_t)node * 32 + lane] = o;
    }

    *(float4*)&shs[ty][lane * 4] = o;
    *(float4*)&shq[ty][lane * 4] = make_float4(o.x * o.x, o.y * o.y, o.z * o.z, o.w * o.w);
    __syncthreads();
    int tid = ty * 32 + lane;
    if (tid < HID) {
        float s = 0.f, q = 0.f;
#pragma unroll
        for (int r = 0; r < 8; r++) { s += shs[r][tid]; q += shq[r][tid]; }
        atomicAdd(&g_cs[layer][tid], s);
        atomicAdd(&g_cq[layer][tid], q);
    }
}

// ---------------- width-10 final agg ----------------
__global__ __launch_bounds__(256) void k_agg10(
    const float* __restrict__ bias, float* __restrict__ out, int n)
{
    int ty = threadIdx.y;
    int lane = threadIdx.x;
    int node = blockIdx.x * 8 + ty;
    if (node >= n) return;
    int half = lane >> 4;
    int c = lane & 15;
    const float* h = (const float*)g_bufB;
    float di = g_dinv[node];
    float acc = 0.f;
    if (half == 0 && c < NOUT) acc = h[(size_t)node * NOUT + c];
    int beg = g_rowstart[node], end = g_rowstart[node + 1];
    int j = beg + half;
    int s = 0;
    bool have = (j < end);
    if (have) s = g_src_sorted[j];
    while (have) {
        int jn = j + 2;
        int sn = 0;
        bool more = (jn < end);
        if (more) sn = g_src_sorted[jn];
        if (c < NOUT) acc += h[(size_t)s * NOUT + c];
        s = sn; j = jn; have = more;
    }
    acc += __shfl_xor_sync(0xffffffffu, acc, 16);
    if (half == 0 && c < NOUT)
        out[(size_t)node * NOUT + c] = fmaf(di, acc, bias[c]);
}

// ---------------- BN finalize ----------------
__global__ __launch_bounds__(128) void k_bnfinal(
    const float* __restrict__ g, const float* __restrict__ be,
    int layer, int n)
{
    int c = threadIdx.x;
    float inv_n = 1.0f / (float)n;
    float mu  = g_cs[layer][c] * inv_n;
    float var = fmaxf(g_cq[layer][c] * inv_n - mu * mu, 0.0f);
    float sc = g[c] * rsqrtf(var + BN_EPS);
    g_scale[c] = sc;
    g_shift[c] = fmaf(-mu, sc, be[c]);
}

// ---------------- host launcher: launches + capture-safe stream fork ----------------
extern "C" void kernel_launch(void* const* d_in, const int* in_sizes, int n_in,
                              void* d_out, int out_size)
{
    const float* x  = (const float*)d_in[0];
    const void*  ei = d_in[1];
    const float* W0 = (const float*)d_in[2];  const float* b0 = (const float*)d_in[3];
    const float* g0 = (const float*)d_in[4];  const float* be0 = (const float*)d_in[5];
    const float* W1 = (const float*)d_in[6];  const float* b1 = (const float*)d_in[7];
    const float* g1 = (const float*)d_in[8];  const float* be1 = (const float*)d_in[9];
    const float* W2 = (const float*)d_in[10]; const float* b2 = (const float*)d_in[11];

    int n = in_sizes[0] / HID;
    int e = in_sizes[1] / 2;
    float* out = (float*)d_out;

    // Stream/events created ONCE on the first (uncaptured correctness) call.
    // No device-memory allocation involved; only launches/event-ops during capture.
    static cudaStream_t s2 = nullptr;
    static cudaEvent_t evFork = nullptr, evJoin = nullptr;
    if (s2 == nullptr) {
        cudaStreamCreateWithFlags(&s2, cudaStreamNonBlocking);
        cudaEventCreateWithFlags(&evFork, cudaEventDisableTiming);
        cudaEventCreateWithFlags(&evJoin, cudaEventDisableTiming);
    }

    int nb_n256 = (n + 255) / 256;
    int nb_scan = (n + SCAN_B - 1) / SCAN_B;
    dim3 aggBlk(32, 8);
    int aggGrid = (n + 7) / 8;
    int gemmGrid = (n + GMB - 1) / GMB;

    // ---- init (both branches depend on it) ----
    k_init<<<nb_n256, 256>>>((const unsigned int*)ei, W0, W1, n);

    // ---- fork: layer-0 GEMM (CSR-independent, unscaled output) on s2 ----
    cudaEventRecord(evFork, 0);
    cudaStreamWaitEvent(s2, evFork, 0);
    k_gemm_tc<<<gemmGrid, 256, 0, s2>>>(x, 0, 0, /*scaleOut=*/0, n);
    cudaEventRecord(evJoin, s2);

    // ---- CSR build on default stream (runs concurrently with gemm0) ----
    if ((e & 3) == 0) {
        int nb_v = ((e >> 2) + 255) / 256;
        k_count4<<<nb_v, 256>>>(ei, e, n);
        k_scan1<<<nb_scan, SCAN_B>>>(n);
        k_scan3<<<nb_n256, 256>>>(n, nb_scan);
        k_bucket4<<<nb_v, 256>>>(ei, e, n);
    } else {
        int nb_e256 = (e + 255) / 256;
        k_count<<<nb_e256, 256>>>(ei, e, n);
        k_scan1<<<nb_scan, SCAN_B>>>(n);
        k_scan3<<<nb_n256, 256>>>(n, nb_scan);
        k_bucket<<<nb_e256, 256>>>(ei, e, n);
    }

    // ---- join, then layer-0 aggregation with per-edge dinv weights ----
    cudaStreamWaitEvent(0, evJoin, 0);
    k_agg128w<<<aggGrid, aggBlk>>>(b0, n, 0);
    k_bnfinal<<<1, 128>>>(g0, be0, 0, n);

    // ---- layer 1 (BN0 apply fused into A-load; dinv pre-scale in epilogue) ----
    k_gemm_tc<<<gemmGrid, 256>>>(x, 1, 1, /*scaleOut=*/1, n);
    k_agg128<<<aggGrid, aggBlk>>>(b1, n, 1);
    k_bnfinal<<<1, 128>>>(g1, be1, 1, n);

    // ---- layer 2 (output) ----
    k_gemm10<<<(n + 7) / 8, 256>>>(W2, n);
    k_agg10<<<aggGrid, aggBlk>>>(b2, out, n);
}